// round 3
// baseline (speedup 1.0000x reference)
#include <cuda_runtime.h>
#include <cstdint>
#include <cstddef>

// ---------------------------------------------------------------------------
// Problem constants
// ---------------------------------------------------------------------------
#define C_DIM   1024
#define H_HEADS 16
#define D_HEAD  64
#define B_BATCH 2
#define LQ      1024
#define LK      4096

// ---------------------------------------------------------------------------
// Device scratch (allocation-free: __device__ globals)
// ---------------------------------------------------------------------------
__device__ float g_q[B_BATCH * H_HEADS * LQ * D_HEAD];   //  8 MB  [B,H,Lq,D]
__device__ float g_k[B_BATCH * H_HEADS * LK * D_HEAD];   // 32 MB  [B,H,Lk,D]
__device__ float g_v[B_BATCH * H_HEADS * LK * D_HEAD];   // 32 MB  [B,H,Lk,D]
__device__ float g_ctx[B_BATCH * LQ * C_DIM];            //  8 MB  [B,Lq,C]

// ---------------------------------------------------------------------------
// Helpers
// ---------------------------------------------------------------------------
__device__ __forceinline__ unsigned f2tf(float f) {
    unsigned u;
    asm volatile("cvt.rna.tf32.f32 %0, %1;" : "=r"(u) : "f"(f));
    return u;
}

// D = A(row-major m16 x k8) * B(col-major k8 x n8) + D  (tf32, fp32 accum)
__device__ __forceinline__ void mma_tf32(float c[4], const unsigned a[4], const unsigned b[2]) {
    asm volatile(
        "mma.sync.aligned.m16n8k8.row.col.f32.tf32.tf32.f32 "
        "{%0,%1,%2,%3}, {%4,%5,%6,%7}, {%8,%9}, {%0,%1,%2,%3};"
        : "+f"(c[0]), "+f"(c[1]), "+f"(c[2]), "+f"(c[3])
        : "r"(a[0]), "r"(a[1]), "r"(a[2]), "r"(a[3]), "r"(b[0]), "r"(b[1]));
}

__device__ __forceinline__ void cp_async16(void* smem, const void* gmem) {
    unsigned sa = (unsigned)__cvta_generic_to_shared(smem);
    asm volatile("cp.async.ca.shared.global [%0], [%1], 16;" :: "r"(sa), "l"(gmem));
}
__device__ __forceinline__ void cp_commit() { asm volatile("cp.async.commit_group;"); }
template <int N>
__device__ __forceinline__ void cp_wait() { asm volatile("cp.async.wait_group %0;" :: "n"(N)); }

// ---------------------------------------------------------------------------
// TF32 GEMM:  out[m,n] = sum_k X[m,k] * W[n,k] + bias[n]
//   X: [M, 1024] row-major (fp32), W: [1024, 1024] row-major ([n,k]) -> B^T form.
//   HEADSPLIT==1: scatter output to [B, H, Lrows, D] (fused head transpose).
//   HEADSPLIT==0: plain [M, 1024] row-major.
// BM=128, BN=128, BK=16, 256 threads (8 warps, 2x4), warp tile 64x32,
// double-buffered cp.async.
// ---------------------------------------------------------------------------
#define GBM 128
#define GBN 128
#define GBK 16
#define KSTR 20  // GBK + 4 pad (conflict-free fragment loads)

__device__ __forceinline__ void gemm_load_stage(
    float* sA, float* sB, const float* __restrict__ X, const float* __restrict__ W,
    int bm, int bn, int k0, int lrow, int lcol4)
{
#pragma unroll
    for (int p = 0; p < 2; p++) {
        int row = lrow + p * 64;
        cp_async16(&sA[row * KSTR + lcol4], &X[(size_t)(bm + row) * C_DIM + k0 + lcol4]);
        cp_async16(&sB[row * KSTR + lcol4], &W[(size_t)(bn + row) * C_DIM + k0 + lcol4]);
    }
    cp_commit();
}

template <int HEADSPLIT>
__global__ __launch_bounds__(256)
void gemm_tf32_kernel(const float* __restrict__ X, const float* __restrict__ W,
                      const float* __restrict__ bias, float* __restrict__ out,
                      int Lrows)
{
    __shared__ float sA[2][GBM * KSTR];
    __shared__ float sB[2][GBN * KSTR];

    const int tid  = threadIdx.x;
    const int bm   = blockIdx.y * GBM;
    const int bn   = blockIdx.x * GBN;
    const int wid  = tid >> 5;
    const int lane = tid & 31;
    const int wm   = (wid & 1) * 64;   // warp row offset within CTA tile
    const int wn   = (wid >> 1) * 32;  // warp col offset within CTA tile
    const int qr   = lane >> 2;        // group id (0..7)
    const int ql   = lane & 3;         // thread-in-group (0..3)

    const int lrow  = tid >> 2;         // 0..63
    const int lcol4 = (tid & 3) * 4;    // 0,4,8,12

    float acc[4][4][4];
#pragma unroll
    for (int i = 0; i < 4; i++)
#pragma unroll
        for (int j = 0; j < 4; j++)
#pragma unroll
            for (int r = 0; r < 4; r++) acc[i][j][r] = 0.f;

    const int NK = C_DIM / GBK;  // 64

    gemm_load_stage(sA[0], sB[0], X, W, bm, bn, 0, lrow, lcol4);

    for (int kt = 0; kt < NK; kt++) {
        const int buf = kt & 1;
        if (kt + 1 < NK) {
            gemm_load_stage(sA[buf ^ 1], sB[buf ^ 1], X, W, bm, bn, (kt + 1) * GBK, lrow, lcol4);
            cp_wait<1>();
        } else {
            cp_wait<0>();
        }
        __syncthreads();

#pragma unroll
        for (int ks = 0; ks < 2; ks++) {
            const int kb = ks * 8;
            unsigned af[4][4], bf[4][2];
#pragma unroll
            for (int mi = 0; mi < 4; mi++) {
                int r0 = wm + mi * 16 + qr;
                af[mi][0] = f2tf(sA[buf][(r0)     * KSTR + kb + ql]);
                af[mi][1] = f2tf(sA[buf][(r0 + 8) * KSTR + kb + ql]);
                af[mi][2] = f2tf(sA[buf][(r0)     * KSTR + kb + ql + 4]);
                af[mi][3] = f2tf(sA[buf][(r0 + 8) * KSTR + kb + ql + 4]);
            }
#pragma unroll
            for (int ni = 0; ni < 4; ni++) {
                int c0 = wn + ni * 8 + qr;
                bf[ni][0] = f2tf(sB[buf][c0 * KSTR + kb + ql]);
                bf[ni][1] = f2tf(sB[buf][c0 * KSTR + kb + ql + 4]);
            }
#pragma unroll
            for (int mi = 0; mi < 4; mi++)
#pragma unroll
                for (int ni = 0; ni < 4; ni++)
                    mma_tf32(acc[mi][ni], af[mi], bf[ni]);
        }
        __syncthreads();
    }

    // Epilogue: add bias, store (optionally head-split scatter)
#pragma unroll
    for (int mi = 0; mi < 4; mi++) {
#pragma unroll
        for (int ni = 0; ni < 4; ni++) {
            const int m0 = bm + wm + mi * 16 + qr;
            const int n0 = bn + wn + ni * 8 + 2 * ql;
            const float b0 = bias[n0], b1 = bias[n0 + 1];
            const float v00 = acc[mi][ni][0] + b0;
            const float v01 = acc[mi][ni][1] + b1;
            const float v10 = acc[mi][ni][2] + b0;
            const float v11 = acc[mi][ni][3] + b1;
            if (HEADSPLIT) {
                const int bz = m0 / Lrows;
                const int l  = m0 - bz * Lrows;
                const int h  = n0 >> 6;
                const int d  = n0 & 63;
                size_t base = (((size_t)(bz * H_HEADS + h) * Lrows) + l) * D_HEAD + d;
                out[base]     = v00;
                out[base + 1] = v01;
                const int bz2 = (m0 + 8) / Lrows;
                const int l2  = (m0 + 8) - bz2 * Lrows;
                size_t base2 = (((size_t)(bz2 * H_HEADS + h) * Lrows) + l2) * D_HEAD + d;
                out[base2]     = v10;
                out[base2 + 1] = v11;
            } else {
                out[(size_t)m0 * C_DIM + n0]           = v00;
                out[(size_t)m0 * C_DIM + n0 + 1]       = v01;
                out[(size_t)(m0 + 8) * C_DIM + n0]     = v10;
                out[(size_t)(m0 + 8) * C_DIM + n0 + 1] = v11;
            }
        }
    }
}

// ---------------------------------------------------------------------------
// Flash attention (online softmax), per CTA: one (b, h, 128-row Q tile).
// 256 threads = 8 warps; warp w owns q rows [w*16, w*16+16).
// Key loop: 64 chunks of 64 keys. logits = (q.k)*scale + V_bias[key].
// ---------------------------------------------------------------------------
#define QT 128
#define KCH 64
#define SQ_STR 68   // row stride (floats) for sQ / sK / sP — conflict-free [row][k] frags
#define SV_STR 72   // row stride for sV — conflict-free [k][n] frags

#define FLASH_SMEM_FLOATS (QT * SQ_STR + KCH * SQ_STR + KCH * SV_STR + QT * SQ_STR + KCH)
#define FLASH_SMEM_BYTES  (FLASH_SMEM_FLOATS * 4)   // 105,728 B

__global__ __launch_bounds__(256, 1)
void flash_kernel(const float* __restrict__ biasAll)
{
    extern __shared__ float sm[];
    float* sQ    = sm;                      // [QT][SQ_STR]
    float* sK    = sQ + QT * SQ_STR;        // [KCH][SQ_STR]
    float* sV    = sK + KCH * SQ_STR;       // [KCH][SV_STR]
    float* sP    = sV + KCH * SV_STR;       // [QT][SQ_STR]
    float* sBias = sP + QT * SQ_STR;        // [KCH]

    const int tid  = threadIdx.x;
    const int w    = tid >> 5;
    const int lane = tid & 31;
    const int qr   = lane >> 2;
    const int ql   = lane & 3;
    const int q0   = blockIdx.x * QT;
    const int h    = blockIdx.y;
    const int b    = blockIdx.z;

    const float* qp = g_q + (size_t)(b * H_HEADS + h) * LQ * D_HEAD;
    const float* kp = g_k + (size_t)(b * H_HEADS + h) * LK * D_HEAD;
    const float* vp = g_v + (size_t)(b * H_HEADS + h) * LK * D_HEAD;
    const float* bp = biasAll + (size_t)b * LK;

    // Load Q tile (128 x 64 fp32) once
#pragma unroll
    for (int it = 0; it < 8; it++) {
        int fid = tid + it * 256;
        int row = fid >> 4;
        int c4  = (fid & 15) * 4;
        float4 v4 = *(const float4*)&qp[(size_t)(q0 + row) * D_HEAD + c4];
        *(float4*)&sQ[row * SQ_STR + c4] = v4;
    }

    float o[8][4];
#pragma unroll
    for (int ni = 0; ni < 8; ni++)
#pragma unroll
        for (int r = 0; r < 4; r++) o[ni][r] = 0.f;

    float row_m[2] = {-1e30f, -1e30f};
    float row_l[2] = {0.f, 0.f};
    const float scale = 0.125f;  // 1/sqrt(64)
    const int r0 = w * 16 + qr;  // this thread's base row within Q tile

    for (int kc0 = 0; kc0 < LK; kc0 += KCH) {
        __syncthreads();  // prior-iteration reads of sK/sV done; also covers sQ fill

        // Load K,V chunk (each 64 x 64 fp32)
#pragma unroll
        for (int it = 0; it < 4; it++) {
            int fid = tid + it * 256;
            int row = fid >> 4;
            int c4  = (fid & 15) * 4;
            *(float4*)&sK[row * SQ_STR + c4] = *(const float4*)&kp[(size_t)(kc0 + row) * D_HEAD + c4];
            *(float4*)&sV[row * SV_STR + c4] = *(const float4*)&vp[(size_t)(kc0 + row) * D_HEAD + c4];
        }
        if (tid < KCH) sBias[tid] = bp[kc0 + tid];
        __syncthreads();

        // S = Q @ K^T  (warp: 16 x 64)
        float s[8][4];
#pragma unroll
        for (int ni = 0; ni < 8; ni++)
#pragma unroll
            for (int r = 0; r < 4; r++) s[ni][r] = 0.f;

#pragma unroll
        for (int kk = 0; kk < 8; kk++) {
            const int kb = kk * 8;
            unsigned af[4];
            af[0] = f2tf(sQ[(r0)     * SQ_STR + kb + ql]);
            af[1] = f2tf(sQ[(r0 + 8) * SQ_STR + kb + ql]);
            af[2] = f2tf(sQ[(r0)     * SQ_STR + kb + ql + 4]);
            af[3] = f2tf(sQ[(r0 + 8) * SQ_STR + kb + ql + 4]);
#pragma unroll
            for (int ni = 0; ni < 8; ni++) {
                unsigned bf[2];
                const int nc = ni * 8 + qr;
                bf[0] = f2tf(sK[nc * SQ_STR + kb + ql]);
                bf[1] = f2tf(sK[nc * SQ_STR + kb + ql + 4]);
                mma_tf32(s[ni], af, bf);
            }
        }

        // scale + per-key bias
#pragma unroll
        for (int ni = 0; ni < 8; ni++) {
            const int c0 = ni * 8 + 2 * ql;
            const float b0 = sBias[c0], b1 = sBias[c0 + 1];
            s[ni][0] = s[ni][0] * scale + b0;
            s[ni][1] = s[ni][1] * scale + b1;
            s[ni][2] = s[ni][2] * scale + b0;
            s[ni][3] = s[ni][3] * scale + b1;
        }

        // Online softmax (rows r0 [half=0] and r0+8 [half=1]); quad shfl reductions
#pragma unroll
        for (int half = 0; half < 2; half++) {
            float mx = -1e30f;
#pragma unroll
            for (int ni = 0; ni < 8; ni++)
                mx = fmaxf(mx, fmaxf(s[ni][2 * half], s[ni][2 * half + 1]));
            mx = fmaxf(mx, __shfl_xor_sync(0xffffffffu, mx, 1));
            mx = fmaxf(mx, __shfl_xor_sync(0xffffffffu, mx, 2));
            const float mnew  = fmaxf(row_m[half], mx);
            const float alpha = __expf(row_m[half] - mnew);
            row_m[half] = mnew;
            float ls = 0.f;
#pragma unroll
            for (int ni = 0; ni < 8; ni++) {
                float e0 = __expf(s[ni][2 * half]     - mnew);
                float e1 = __expf(s[ni][2 * half + 1] - mnew);
                s[ni][2 * half]     = e0;
                s[ni][2 * half + 1] = e1;
                ls += e0 + e1;
            }
            ls += __shfl_xor_sync(0xffffffffu, ls, 1);
            ls += __shfl_xor_sync(0xffffffffu, ls, 2);
            row_l[half] = row_l[half] * alpha + ls;
#pragma unroll
            for (int ni = 0; ni < 8; ni++) {
                o[ni][2 * half]     *= alpha;
                o[ni][2 * half + 1] *= alpha;
            }
        }

        // P -> smem (C-fragment layout != A-fragment layout; warp-local round trip)
#pragma unroll
        for (int ni = 0; ni < 8; ni++) {
            const int c0 = ni * 8 + 2 * ql;
            sP[(r0)     * SQ_STR + c0]     = s[ni][0];
            sP[(r0)     * SQ_STR + c0 + 1] = s[ni][1];
            sP[(r0 + 8) * SQ_STR + c0]     = s[ni][2];
            sP[(r0 + 8) * SQ_STR + c0 + 1] = s[ni][3];
        }
        __syncwarp();  // each warp reads only its own 16 P rows

        // O += P @ V
#pragma unroll
        for (int kk = 0; kk < 8; kk++) {
            const int kb = kk * 8;
            unsigned af[4];
            af[0] = f2tf(sP[(r0)     * SQ_STR + kb + ql]);
            af[1] = f2tf(sP[(r0 + 8) * SQ_STR + kb + ql]);
            af[2] = f2tf(sP[(r0)     * SQ_STR + kb + ql + 4]);
            af[3] = f2tf(sP[(r0 + 8) * SQ_STR + kb + ql + 4]);
#pragma unroll
            for (int ni = 0; ni < 8; ni++) {
                unsigned bf[2];
                const int nc = ni * 8 + qr;
                bf[0] = f2tf(sV[(kb + ql)     * SV_STR + nc]);
                bf[1] = f2tf(sV[(kb + ql + 4) * SV_STR + nc]);
                mma_tf32(o[ni], af, bf);
            }
        }
    }

    // Normalize and write context [B, Lq, C] (c = h*64 + d)
    const float inv0 = 1.f / row_l[0];
    const float inv1 = 1.f / row_l[1];
    float* ctx = g_ctx + (size_t)b * LQ * C_DIM;
    const int rA = q0 + r0;
#pragma unroll
    for (int ni = 0; ni < 8; ni++) {
        const int col = h * 64 + ni * 8 + 2 * ql;
        ctx[(size_t)rA * C_DIM + col]           = o[ni][0] * inv0;
        ctx[(size_t)rA * C_DIM + col + 1]       = o[ni][1] * inv0;
        ctx[(size_t)(rA + 8) * C_DIM + col]     = o[ni][2] * inv1;
        ctx[(size_t)(rA + 8) * C_DIM + col + 1] = o[ni][3] * inv1;
    }
}

// ---------------------------------------------------------------------------
// kernel_launch: 5 stream-ordered launches (graph-capturable, alloc-free)
// ---------------------------------------------------------------------------
extern "C" void kernel_launch(void* const* d_in, const int* in_sizes, int n_in,
                              void* d_out, int out_size)
{
    const float* Q      = (const float*)d_in[0];
    const float* K_in   = (const float*)d_in[1];
    const float* V_in   = (const float*)d_in[2];
    const float* V_bias = (const float*)d_in[3];
    const float* Wq_w   = (const float*)d_in[4];
    const float* Wq_b   = (const float*)d_in[5];
    const float* Wk_w   = (const float*)d_in[6];
    const float* Wk_b   = (const float*)d_in[7];
    const float* Wv_w   = (const float*)d_in[8];
    const float* Wv_b   = (const float*)d_in[9];
    const float* Wo_w   = (const float*)d_in[10];
    const float* Wo_b   = (const float*)d_in[11];

    float *qptr = nullptr, *kptr = nullptr, *vptr = nullptr, *ctxptr = nullptr;
    cudaGetSymbolAddress((void**)&qptr,   g_q);
    cudaGetSymbolAddress((void**)&kptr,   g_k);
    cudaGetSymbolAddress((void**)&vptr,   g_v);
    cudaGetSymbolAddress((void**)&ctxptr, g_ctx);

    cudaFuncSetAttribute(flash_kernel,
                         cudaFuncAttributeMaxDynamicSharedMemorySize,
                         FLASH_SMEM_BYTES);

    // Q projection: [2048,1024] @ Wq^T -> head-split [B,H,Lq,D]
    gemm_tf32_kernel<1><<<dim3(C_DIM / GBN, (B_BATCH * LQ) / GBM), 256>>>(Q, Wq_w, Wq_b, qptr, LQ);
    // K projection: [8192,1024] -> [B,H,Lk,D]
    gemm_tf32_kernel<1><<<dim3(C_DIM / GBN, (B_BATCH * LK) / GBM), 256>>>(K_in, Wk_w, Wk_b, kptr, LK);
    // V projection
    gemm_tf32_kernel<1><<<dim3(C_DIM / GBN, (B_BATCH * LK) / GBM), 256>>>(V_in, Wv_w, Wv_b, vptr, LK);

    // Attention
    flash_kernel<<<dim3(LQ / QT, H_HEADS, B_BATCH), 256, FLASH_SMEM_BYTES>>>(V_bias);

    // Output projection: ctx [2048,1024] @ Wo^T + b -> d_out
    gemm_tf32_kernel<0><<<dim3(C_DIM / GBN, (B_BATCH * LQ) / GBM), 256>>>(ctxptr, Wo_w, Wo_b, (float*)d_out, 1);
}

// round 4
// speedup vs baseline: 1.0691x; 1.0691x over previous
#include <cuda_runtime.h>
#include <cstdint>
#include <cstddef>

// ---------------------------------------------------------------------------
// Problem constants
// ---------------------------------------------------------------------------
#define C_DIM   1024
#define H_HEADS 16
#define D_HEAD  64
#define B_BATCH 2
#define LQ      1024
#define LK      4096

// ---------------------------------------------------------------------------
// Device scratch (allocation-free: __device__ globals)
// ---------------------------------------------------------------------------
__device__ float g_q[B_BATCH * H_HEADS * LQ * D_HEAD];   //  8 MB  [B,H,Lq,D]
__device__ float g_k[B_BATCH * H_HEADS * LK * D_HEAD];   // 32 MB  [B,H,Lk,D]
__device__ float g_v[B_BATCH * H_HEADS * LK * D_HEAD];   // 32 MB  [B,H,Lk,D]
__device__ float g_ctx[B_BATCH * LQ * C_DIM];            //  8 MB  [B,Lq,C]

// ---------------------------------------------------------------------------
// Helpers
// ---------------------------------------------------------------------------
__device__ __forceinline__ unsigned f2tf(float f) {
    unsigned u;
    asm volatile("cvt.rna.tf32.f32 %0, %1;" : "=r"(u) : "f"(f));
    return u;
}
__device__ __forceinline__ float ex2f(float x) {
    float y;
    asm volatile("ex2.approx.f32 %0, %1;" : "=f"(y) : "f"(x));
    return y;
}

// D = A(row-major m16 x k8) * B(col-major k8 x n8) + D  (tf32, fp32 accum)
__device__ __forceinline__ void mma_tf32(float c[4], const unsigned a[4], const unsigned b[2]) {
    asm volatile(
        "mma.sync.aligned.m16n8k8.row.col.f32.tf32.tf32.f32 "
        "{%0,%1,%2,%3}, {%4,%5,%6,%7}, {%8,%9}, {%0,%1,%2,%3};"
        : "+f"(c[0]), "+f"(c[1]), "+f"(c[2]), "+f"(c[3])
        : "r"(a[0]), "r"(a[1]), "r"(a[2]), "r"(a[3]), "r"(b[0]), "r"(b[1]));
}

__device__ __forceinline__ void cp_async16(void* smem, const void* gmem) {
    unsigned sa = (unsigned)__cvta_generic_to_shared(smem);
    asm volatile("cp.async.ca.shared.global [%0], [%1], 16;" :: "r"(sa), "l"(gmem));
}
__device__ __forceinline__ void cp_commit() { asm volatile("cp.async.commit_group;"); }
template <int N>
__device__ __forceinline__ void cp_wait() { asm volatile("cp.async.wait_group %0;" :: "n"(N)); }

// ---------------------------------------------------------------------------
// TF32 GEMM:  out[m,n] = sum_k X[m,k] * W[n,k] + bias[n]
//   SMEM holds pre-converted tf32 bits. LDG register-prefetch pipeline,
//   cvt folded into STS, one __syncthreads per k-tile.
// BM=128, BN=128, BK=16, 256 threads (8 warps, 2x4), warp tile 64x32.
// ---------------------------------------------------------------------------
#define GBM 128
#define GBN 128
#define GBK 16
#define KSTR 20  // GBK + 4 pad (conflict-free fragment loads)

__device__ __forceinline__ void gemm_ldg(
    float4 ra[2], float4 rb[2],
    const float* __restrict__ X, const float* __restrict__ W,
    int bm, int bn, int k0, int tid)
{
#pragma unroll
    for (int p = 0; p < 2; p++) {
        int f   = tid + p * 256;       // 0..511 float4 slots per matrix
        int row = f >> 2;              // 0..127
        int c4  = (f & 3) * 4;         // 0,4,8,12
        ra[p] = *(const float4*)&X[(size_t)(bm + row) * C_DIM + k0 + c4];
        rb[p] = *(const float4*)&W[(size_t)(bn + row) * C_DIM + k0 + c4];
    }
}

__device__ __forceinline__ void gemm_sts(
    unsigned* sA, unsigned* sB, const float4 ra[2], const float4 rb[2], int tid)
{
#pragma unroll
    for (int p = 0; p < 2; p++) {
        int f   = tid + p * 256;
        int row = f >> 2;
        int c4  = (f & 3) * 4;
        uint4 ua, ub;
        ua.x = f2tf(ra[p].x); ua.y = f2tf(ra[p].y); ua.z = f2tf(ra[p].z); ua.w = f2tf(ra[p].w);
        ub.x = f2tf(rb[p].x); ub.y = f2tf(rb[p].y); ub.z = f2tf(rb[p].z); ub.w = f2tf(rb[p].w);
        *(uint4*)&sA[row * KSTR + c4] = ua;
        *(uint4*)&sB[row * KSTR + c4] = ub;
    }
}

template <int HEADSPLIT>
__global__ __launch_bounds__(256, 2)
void gemm_tf32_kernel(const float* __restrict__ X, const float* __restrict__ W,
                      const float* __restrict__ bias, float* __restrict__ out,
                      int Lrows)
{
    __shared__ unsigned sA[2][GBM * KSTR];
    __shared__ unsigned sB[2][GBN * KSTR];

    const int tid  = threadIdx.x;
    const int bm   = blockIdx.y * GBM;
    const int bn   = blockIdx.x * GBN;
    const int wid  = tid >> 5;
    const int lane = tid & 31;
    const int wm   = (wid & 1) * 64;
    const int wn   = (wid >> 1) * 32;
    const int qr   = lane >> 2;
    const int ql   = lane & 3;

    float acc[4][4][4];
#pragma unroll
    for (int i = 0; i < 4; i++)
#pragma unroll
        for (int j = 0; j < 4; j++)
#pragma unroll
            for (int r = 0; r < 4; r++) acc[i][j][r] = 0.f;

    const int NK = C_DIM / GBK;  // 64

    {   // prologue: stage kt=0
        float4 ra[2], rb[2];
        gemm_ldg(ra, rb, X, W, bm, bn, 0, tid);
        gemm_sts(sA[0], sB[0], ra, rb, tid);
    }
    __syncthreads();

    for (int kt = 0; kt < NK; kt++) {
        const int buf = kt & 1;
        float4 ra[2], rb[2];
        if (kt + 1 < NK) gemm_ldg(ra, rb, X, W, bm, bn, (kt + 1) * GBK, tid);

#pragma unroll
        for (int ks = 0; ks < 2; ks++) {
            const int kb = ks * 8;
            unsigned af[4][4], bf[4][2];
#pragma unroll
            for (int mi = 0; mi < 4; mi++) {
                int r0 = wm + mi * 16 + qr;
                af[mi][0] = sA[buf][(r0)     * KSTR + kb + ql];
                af[mi][1] = sA[buf][(r0 + 8) * KSTR + kb + ql];
                af[mi][2] = sA[buf][(r0)     * KSTR + kb + ql + 4];
                af[mi][3] = sA[buf][(r0 + 8) * KSTR + kb + ql + 4];
            }
#pragma unroll
            for (int ni = 0; ni < 4; ni++) {
                int c0 = wn + ni * 8 + qr;
                bf[ni][0] = sB[buf][c0 * KSTR + kb + ql];
                bf[ni][1] = sB[buf][c0 * KSTR + kb + ql + 4];
            }
#pragma unroll
            for (int mi = 0; mi < 4; mi++)
#pragma unroll
                for (int ni = 0; ni < 4; ni++)
                    mma_tf32(acc[mi][ni], af[mi], bf[ni]);
        }

        if (kt + 1 < NK) gemm_sts(sA[buf ^ 1], sB[buf ^ 1], ra, rb, tid);
        __syncthreads();
    }

    // Epilogue: add bias, store (optionally head-split scatter)
#pragma unroll
    for (int mi = 0; mi < 4; mi++) {
#pragma unroll
        for (int ni = 0; ni < 4; ni++) {
            const int m0 = bm + wm + mi * 16 + qr;
            const int n0 = bn + wn + ni * 8 + 2 * ql;
            const float b0 = bias[n0], b1 = bias[n0 + 1];
            const float v00 = acc[mi][ni][0] + b0;
            const float v01 = acc[mi][ni][1] + b1;
            const float v10 = acc[mi][ni][2] + b0;
            const float v11 = acc[mi][ni][3] + b1;
            if (HEADSPLIT) {
                const int bz = m0 / Lrows;
                const int l  = m0 - bz * Lrows;
                const int h  = n0 >> 6;
                const int d  = n0 & 63;
                size_t base = (((size_t)(bz * H_HEADS + h) * Lrows) + l) * D_HEAD + d;
                out[base]     = v00;
                out[base + 1] = v01;
                const int bz2 = (m0 + 8) / Lrows;
                const int l2  = (m0 + 8) - bz2 * Lrows;
                size_t base2 = (((size_t)(bz2 * H_HEADS + h) * Lrows) + l2) * D_HEAD + d;
                out[base2]     = v10;
                out[base2 + 1] = v11;
            } else {
                out[(size_t)m0 * C_DIM + n0]           = v00;
                out[(size_t)m0 * C_DIM + n0 + 1]       = v01;
                out[(size_t)(m0 + 8) * C_DIM + n0]     = v10;
                out[(size_t)(m0 + 8) * C_DIM + n0 + 1] = v11;
            }
        }
    }
}

// ---------------------------------------------------------------------------
// Flash attention (online softmax), per CTA: one (b, h, 128-row Q tile).
// 256 threads = 8 warps; warp w owns q rows [w*16, w*16+16).
// SMEM holds tf32 bits (converted once per element). Single-buffered K and V
// with split cp.async pipeline: K(i+1) arrives during softmax+PV(i),
// V(i+1) arrives during S(i+1). 2 CTAs/SM.
// Softmax in log2 domain (ex2.approx), log2(e) folded into scale/bias.
// ---------------------------------------------------------------------------
#define QT 128
#define KCH 64
#define SQ_STR 68   // conflict-free [row][k] fragment reads
#define SV_STR 72   // conflict-free [k][n] fragment reads

#define FLASH_SMEM_WORDS (QT * SQ_STR + KCH * SQ_STR + KCH * SV_STR + QT * SQ_STR + KCH)
#define FLASH_SMEM_BYTES (FLASH_SMEM_WORDS * 4)   // 105,728 B  (x2 CTAs = 211.5 KB <= 228 KB)

#define LOG2E 1.4426950408889634f

__global__ __launch_bounds__(256, 2)
void flash_kernel(const float* __restrict__ biasAll)
{
    extern __shared__ unsigned smu[];
    unsigned* uQ    = smu;                    // [QT][SQ_STR] tf32 bits
    unsigned* uK    = uQ + QT * SQ_STR;       // [KCH][SQ_STR]
    unsigned* uV    = uK + KCH * SQ_STR;      // [KCH][SV_STR]
    unsigned* uP    = uV + KCH * SV_STR;      // [QT][SQ_STR]
    float*    fBias = (float*)(uP + QT * SQ_STR);  // [KCH] (log2e-scaled)

    const int tid  = threadIdx.x;
    const int w    = tid >> 5;
    const int lane = tid & 31;
    const int qr   = lane >> 2;
    const int ql   = lane & 3;
    const int q0   = blockIdx.x * QT;
    const int h    = blockIdx.y;
    const int b    = blockIdx.z;

    const float* qp = g_q + (size_t)(b * H_HEADS + h) * LQ * D_HEAD;
    const float* kp = g_k + (size_t)(b * H_HEADS + h) * LK * D_HEAD;
    const float* vp = g_v + (size_t)(b * H_HEADS + h) * LK * D_HEAD;
    const float* bp = biasAll + (size_t)b * LK;

    // ---- prologue: async-stage K0 (+bias0), then V0, then fill Q ----
    {
#pragma unroll
        for (int it = 0; it < 4; it++) {
            int f   = tid + it * 256;
            int row = f >> 4;
            int c4  = (f & 15) * 4;
            cp_async16(&uK[row * SQ_STR + c4], &kp[(size_t)row * D_HEAD + c4]);
        }
        if (tid < 16) cp_async16(&fBias[tid * 4], &bp[tid * 4]);
        cp_commit();                       // group: K0+bias0
#pragma unroll
        for (int it = 0; it < 4; it++) {
            int f   = tid + it * 256;
            int row = f >> 4;
            int c4  = (f & 15) * 4;
            cp_async16(&uV[row * SV_STR + c4], &vp[(size_t)row * D_HEAD + c4]);
        }
        cp_commit();                       // group: V0
    }
    // Q tile -> tf32 bits in smem (once)
#pragma unroll
    for (int it = 0; it < 8; it++) {
        int f   = tid + it * 256;
        int row = f >> 4;
        int c4  = (f & 15) * 4;
        float4 v4 = *(const float4*)&qp[(size_t)(q0 + row) * D_HEAD + c4];
        uint4 u4;
        u4.x = f2tf(v4.x); u4.y = f2tf(v4.y); u4.z = f2tf(v4.z); u4.w = f2tf(v4.w);
        *(uint4*)&uQ[row * SQ_STR + c4] = u4;
    }

    float o[8][4];
#pragma unroll
    for (int ni = 0; ni < 8; ni++)
#pragma unroll
        for (int r = 0; r < 4; r++) o[ni][r] = 0.f;

    float row_m[2] = {-1e30f, -1e30f};   // log2-domain running max
    float row_l[2] = {0.f, 0.f};
    const float scl = 0.125f * LOG2E;    // (1/sqrt(64)) * log2(e)
    const int r0 = w * 16 + qr;

    const int NCH = LK / KCH;  // 64
    for (int i = 0; i < NCH; i++) {
        const int kc0 = i * KCH;

        // ---- K_i arrived (all but last group complete) ----
        cp_wait<1>();
        // cvt own K slice in place (same mapping as the cp.async fill)
#pragma unroll
        for (int it = 0; it < 4; it++) {
            int f   = tid + it * 256;
            int row = f >> 4;
            int c4  = (f & 15) * 4;
            float4 v4 = *(float4*)&uK[row * SQ_STR + c4];
            uint4 u4;
            u4.x = f2tf(v4.x); u4.y = f2tf(v4.y); u4.z = f2tf(v4.z); u4.w = f2tf(v4.w);
            *(uint4*)&uK[row * SQ_STR + c4] = u4;
        }
        if (tid < 16) {
            float4 bv = *(float4*)&fBias[tid * 4];
            bv.x *= LOG2E; bv.y *= LOG2E; bv.z *= LOG2E; bv.w *= LOG2E;
            *(float4*)&fBias[tid * 4] = bv;
        }
        __syncthreads();   // #1: K + bias visible to all warps

        // ---- S = Q @ K^T ----
        float s[8][4];
#pragma unroll
        for (int ni = 0; ni < 8; ni++)
#pragma unroll
            for (int r = 0; r < 4; r++) s[ni][r] = 0.f;

#pragma unroll
        for (int kk = 0; kk < 8; kk++) {
            const int kb = kk * 8;
            unsigned af[4];
            af[0] = uQ[(r0)     * SQ_STR + kb + ql];
            af[1] = uQ[(r0 + 8) * SQ_STR + kb + ql];
            af[2] = uQ[(r0)     * SQ_STR + kb + ql + 4];
            af[3] = uQ[(r0 + 8) * SQ_STR + kb + ql + 4];
#pragma unroll
            for (int ni = 0; ni < 8; ni++) {
                unsigned bf[2];
                const int nc = ni * 8 + qr;
                bf[0] = uK[nc * SQ_STR + kb + ql];
                bf[1] = uK[nc * SQ_STR + kb + ql + 4];
                mma_tf32(s[ni], af, bf);
            }
        }

        // scale + per-key bias (log2 domain)
#pragma unroll
        for (int ni = 0; ni < 8; ni++) {
            const int c0 = ni * 8 + 2 * ql;
            const float b0 = fBias[c0], b1 = fBias[c0 + 1];
            s[ni][0] = fmaf(s[ni][0], scl, b0);
            s[ni][1] = fmaf(s[ni][1], scl, b1);
            s[ni][2] = fmaf(s[ni][2], scl, b0);
            s[ni][3] = fmaf(s[ni][3], scl, b1);
        }
        __syncthreads();   // #2: all warps done with K + bias

        // ---- prefetch K(i+1) (+bias) while softmax+PV run ----
        if (i + 1 < NCH) {
#pragma unroll
            for (int it = 0; it < 4; it++) {
                int f   = tid + it * 256;
                int row = f >> 4;
                int c4  = (f & 15) * 4;
                cp_async16(&uK[row * SQ_STR + c4],
                           &kp[(size_t)(kc0 + KCH + row) * D_HEAD + c4]);
            }
            if (tid < 16) cp_async16(&fBias[tid * 4], &bp[kc0 + KCH + tid * 4]);
            cp_commit();
        }

        // ---- online softmax (rows r0, r0+8); quad shfl reductions ----
#pragma unroll
        for (int half = 0; half < 2; half++) {
            float mx = -1e30f;
#pragma unroll
            for (int ni = 0; ni < 8; ni++)
                mx = fmaxf(mx, fmaxf(s[ni][2 * half], s[ni][2 * half + 1]));
            mx = fmaxf(mx, __shfl_xor_sync(0xffffffffu, mx, 1));
            mx = fmaxf(mx, __shfl_xor_sync(0xffffffffu, mx, 2));
            const float mnew  = fmaxf(row_m[half], mx);
            const float alpha = ex2f(row_m[half] - mnew);
            row_m[half] = mnew;
            float ls = 0.f;
#pragma unroll
            for (int ni = 0; ni < 8; ni++) {
                float e0 = ex2f(s[ni][2 * half]     - mnew);
                float e1 = ex2f(s[ni][2 * half + 1] - mnew);
                s[ni][2 * half]     = e0;
                s[ni][2 * half + 1] = e1;
                ls += e0 + e1;
            }
            ls += __shfl_xor_sync(0xffffffffu, ls, 1);
            ls += __shfl_xor_sync(0xffffffffu, ls, 2);
            row_l[half] = row_l[half] * alpha + ls;
#pragma unroll
            for (int ni = 0; ni < 8; ni++) {
                o[ni][2 * half]     *= alpha;
                o[ni][2 * half + 1] *= alpha;
            }
        }

        // ---- V_i arrived ----
        if (i + 1 < NCH) cp_wait<1>(); else cp_wait<0>();
        // cvt own V slice in place
#pragma unroll
        for (int it = 0; it < 4; it++) {
            int f   = tid + it * 256;
            int row = f >> 4;
            int c4  = (f & 15) * 4;
            float4 v4 = *(float4*)&uV[row * SV_STR + c4];
            uint4 u4;
            u4.x = f2tf(v4.x); u4.y = f2tf(v4.y); u4.z = f2tf(v4.z); u4.w = f2tf(v4.w);
            *(uint4*)&uV[row * SV_STR + c4] = u4;
        }
        // P -> smem as tf32 bits (C-fragment -> A-fragment round trip)
#pragma unroll
        for (int ni = 0; ni < 8; ni++) {
            const int c0 = ni * 8 + 2 * ql;
            uint2 p0, p1;
            p0.x = f2tf(s[ni][0]); p0.y = f2tf(s[ni][1]);
            p1.x = f2tf(s[ni][2]); p1.y = f2tf(s[ni][3]);
            *(uint2*)&uP[(r0)     * SQ_STR + c0] = p0;
            *(uint2*)&uP[(r0 + 8) * SQ_STR + c0] = p1;
        }
        __syncthreads();   // #3: V (+P) visible

        // ---- O += P @ V ----
#pragma unroll
        for (int kk = 0; kk < 8; kk++) {
            const int kb = kk * 8;
            unsigned af[4];
            af[0] = uP[(r0)     * SQ_STR + kb + ql];
            af[1] = uP[(r0 + 8) * SQ_STR + kb + ql];
            af[2] = uP[(r0)     * SQ_STR + kb + ql + 4];
            af[3] = uP[(r0 + 8) * SQ_STR + kb + ql + 4];
#pragma unroll
            for (int ni = 0; ni < 8; ni++) {
                unsigned bf[2];
                const int nc = ni * 8 + qr;
                bf[0] = uV[(kb + ql)     * SV_STR + nc];
                bf[1] = uV[(kb + ql + 4) * SV_STR + nc];
                mma_tf32(o[ni], af, bf);
            }
        }
        __syncthreads();   // #4: all warps done with V

        // ---- prefetch V(i+1) ----
        if (i + 1 < NCH) {
#pragma unroll
            for (int it = 0; it < 4; it++) {
                int f   = tid + it * 256;
                int row = f >> 4;
                int c4  = (f & 15) * 4;
                cp_async16(&uV[row * SV_STR + c4],
                           &vp[(size_t)(kc0 + KCH + row) * D_HEAD + c4]);
            }
            cp_commit();
        }
    }

    // ---- normalize and write context [B, Lq, C] (c = h*64 + d) ----
    const float inv0 = __fdividef(1.f, row_l[0]);
    const float inv1 = __fdividef(1.f, row_l[1]);
    float* ctx = g_ctx + (size_t)b * LQ * C_DIM;
    const int rA = q0 + r0;
#pragma unroll
    for (int ni = 0; ni < 8; ni++) {
        const int col = h * 64 + ni * 8 + 2 * ql;
        ctx[(size_t)rA * C_DIM + col]           = o[ni][0] * inv0;
        ctx[(size_t)rA * C_DIM + col + 1]       = o[ni][1] * inv0;
        ctx[(size_t)(rA + 8) * C_DIM + col]     = o[ni][2] * inv1;
        ctx[(size_t)(rA + 8) * C_DIM + col + 1] = o[ni][3] * inv1;
    }
}

// ---------------------------------------------------------------------------
// kernel_launch: 5 stream-ordered launches (graph-capturable, alloc-free)
// ---------------------------------------------------------------------------
extern "C" void kernel_launch(void* const* d_in, const int* in_sizes, int n_in,
                              void* d_out, int out_size)
{
    const float* Q      = (const float*)d_in[0];
    const float* K_in   = (const float*)d_in[1];
    const float* V_in   = (const float*)d_in[2];
    const float* V_bias = (const float*)d_in[3];
    const float* Wq_w   = (const float*)d_in[4];
    const float* Wq_b   = (const float*)d_in[5];
    const float* Wk_w   = (const float*)d_in[6];
    const float* Wk_b   = (const float*)d_in[7];
    const float* Wv_w   = (const float*)d_in[8];
    const float* Wv_b   = (const float*)d_in[9];
    const float* Wo_w   = (const float*)d_in[10];
    const float* Wo_b   = (const float*)d_in[11];

    float *qptr = nullptr, *kptr = nullptr, *vptr = nullptr, *ctxptr = nullptr;
    cudaGetSymbolAddress((void**)&qptr,   g_q);
    cudaGetSymbolAddress((void**)&kptr,   g_k);
    cudaGetSymbolAddress((void**)&vptr,   g_v);
    cudaGetSymbolAddress((void**)&ctxptr, g_ctx);

    cudaFuncSetAttribute(flash_kernel,
                         cudaFuncAttributeMaxDynamicSharedMemorySize,
                         FLASH_SMEM_BYTES);

    // Q projection: [2048,1024] @ Wq^T -> head-split [B,H,Lq,D]
    gemm_tf32_kernel<1><<<dim3(C_DIM / GBN, (B_BATCH * LQ) / GBM), 256>>>(Q, Wq_w, Wq_b, qptr, LQ);
    // K projection: [8192,1024] -> [B,H,Lk,D]
    gemm_tf32_kernel<1><<<dim3(C_DIM / GBN, (B_BATCH * LK) / GBM), 256>>>(K_in, Wk_w, Wk_b, kptr, LK);
    // V projection
    gemm_tf32_kernel<1><<<dim3(C_DIM / GBN, (B_BATCH * LK) / GBM), 256>>>(V_in, Wv_w, Wv_b, vptr, LK);

    // Attention
    flash_kernel<<<dim3(LQ / QT, H_HEADS, B_BATCH), 256, FLASH_SMEM_BYTES>>>(V_bias);

    // Output projection: ctx [2048,1024] @ Wo^T + b -> d_out
    gemm_tf32_kernel<0><<<dim3(C_DIM / GBN, (B_BATCH * LQ) / GBM), 256>>>(ctxptr, Wo_w, Wo_b, (float*)d_out, 1);
}

// round 5
// speedup vs baseline: 1.2356x; 1.1558x over previous
#include <cuda_runtime.h>
#include <cstdint>
#include <cstddef>

// ---------------------------------------------------------------------------
// Problem constants
// ---------------------------------------------------------------------------
#define C_DIM   1024
#define H_HEADS 16
#define D_HEAD  64
#define B_BATCH 2
#define LQ      1024
#define LK      4096

// ---------------------------------------------------------------------------
// Device scratch (allocation-free: __device__ globals). All tf32 bit patterns.
// ---------------------------------------------------------------------------
__device__ unsigned g_q[B_BATCH * H_HEADS * LQ * D_HEAD];   //  8 MB [B,H,Lq,D]
__device__ unsigned g_k[B_BATCH * H_HEADS * LK * D_HEAD];   // 32 MB [B,H,Lk,D]
__device__ unsigned g_v[B_BATCH * H_HEADS * LK * D_HEAD];   // 32 MB [B,H,Lk,D]
__device__ unsigned g_ctx[B_BATCH * LQ * C_DIM];            //  8 MB [B,Lq,C]
__device__ unsigned g_xq[B_BATCH * LQ * C_DIM];             //  8 MB  pre-cvt Q
__device__ unsigned g_xk[B_BATCH * LK * C_DIM];             // 32 MB  pre-cvt K_in
__device__ unsigned g_xv[B_BATCH * LK * C_DIM];             // 32 MB  pre-cvt V_in
__device__ unsigned g_wt[4 * C_DIM * C_DIM];                // 16 MB  pre-cvt Wq/Wk/Wv/Wo

// ---------------------------------------------------------------------------
// Helpers
// ---------------------------------------------------------------------------
__device__ __forceinline__ unsigned f2tf(float f) {
    unsigned u;
    asm volatile("cvt.rna.tf32.f32 %0, %1;" : "=r"(u) : "f"(f));
    return u;
}
__device__ __forceinline__ float ex2f(float x) {
    float y;
    asm volatile("ex2.approx.f32 %0, %1;" : "=f"(y) : "f"(x));
    return y;
}

// D = A(row-major m16 x k8) * B(col-major k8 x n8) + D  (tf32, fp32 accum)
__device__ __forceinline__ void mma_tf32(float c[4], const unsigned a[4], const unsigned b[2]) {
    asm volatile(
        "mma.sync.aligned.m16n8k8.row.col.f32.tf32.tf32.f32 "
        "{%0,%1,%2,%3}, {%4,%5,%6,%7}, {%8,%9}, {%0,%1,%2,%3};"
        : "+f"(c[0]), "+f"(c[1]), "+f"(c[2]), "+f"(c[3])
        : "r"(a[0]), "r"(a[1]), "r"(a[2]), "r"(a[3]), "r"(b[0]), "r"(b[1]));
}

__device__ __forceinline__ void cp_async16(void* smem, const void* gmem) {
    unsigned sa = (unsigned)__cvta_generic_to_shared(smem);
    asm volatile("cp.async.ca.shared.global [%0], [%1], 16;" :: "r"(sa), "l"(gmem));
}
__device__ __forceinline__ void cp_commit() { asm volatile("cp.async.commit_group;"); }
template <int N>
__device__ __forceinline__ void cp_wait() { asm volatile("cp.async.wait_group %0;" :: "n"(N)); }

// ---------------------------------------------------------------------------
// Pre-convert pass: fp32 -> tf32 bits for the 3 X inputs and 4 W matrices.
// Single grid-stride launch over all regions (memory-bound, ~30us).
// ---------------------------------------------------------------------------
#define N4_Q  (B_BATCH * LQ * C_DIM / 4)   // 524288
#define N4_K  (B_BATCH * LK * C_DIM / 4)   // 2097152
#define N4_W  (C_DIM * C_DIM / 4)          // 262144

__global__ __launch_bounds__(512)
void precvt_kernel(const float4* __restrict__ Q, const float4* __restrict__ K,
                   const float4* __restrict__ V, const float4* __restrict__ Wq,
                   const float4* __restrict__ Wk, const float4* __restrict__ Wv,
                   const float4* __restrict__ Wo)
{
    const int total = N4_Q + 2 * N4_K + 4 * N4_W;
    for (int i = blockIdx.x * blockDim.x + threadIdx.x; i < total;
         i += gridDim.x * blockDim.x) {
        const float4* s;
        uint4* d;
        int j = i;
        if (j < N4_Q)              { s = Q; d = (uint4*)g_xq; }
        else if ((j -= N4_Q) < N4_K) { s = K; d = (uint4*)g_xk; }
        else if ((j -= N4_K) < N4_K) { s = V; d = (uint4*)g_xv; }
        else {
            j -= N4_K;
            int w = j / N4_W;
            j -= w * N4_W;
            s = (w == 0) ? Wq : (w == 1) ? Wk : (w == 2) ? Wv : Wo;
            d = (uint4*)g_wt + (size_t)w * N4_W;
        }
        float4 v = s[j];
        uint4 u;
        u.x = f2tf(v.x); u.y = f2tf(v.y); u.z = f2tf(v.z); u.w = f2tf(v.w);
        d[j] = u;
    }
}

// ---------------------------------------------------------------------------
// TF32 GEMM:  out[m,n] = sum_k X[m,k] * W[n,k] + bias[n]
//   X, W already tf32 bits. cp.async double-buffered (R3 pipeline), no cvt.
//   HEADSPLIT==1: scatter tf32 bits to [B,H,Lrows,D]. HEADSPLIT==0: fp32 [M,C].
// BM=128, BN=128, BK=16, 256 threads (8 warps, 2x4), warp tile 64x32.
// ---------------------------------------------------------------------------
#define GBM 128
#define GBN 128
#define GBK 16
#define KSTR 20  // GBK + 4 pad (conflict-free fragment loads)

__device__ __forceinline__ void gemm_load_stage(
    unsigned* sA, unsigned* sB, const unsigned* __restrict__ X,
    const unsigned* __restrict__ W, int bm, int bn, int k0, int lrow, int lcol4)
{
#pragma unroll
    for (int p = 0; p < 2; p++) {
        int row = lrow + p * 64;
        cp_async16(&sA[row * KSTR + lcol4], &X[(size_t)(bm + row) * C_DIM + k0 + lcol4]);
        cp_async16(&sB[row * KSTR + lcol4], &W[(size_t)(bn + row) * C_DIM + k0 + lcol4]);
    }
    cp_commit();
}

template <int HEADSPLIT>
__global__ __launch_bounds__(256, 2)
void gemm_tf32_kernel(const unsigned* __restrict__ X, const unsigned* __restrict__ W,
                      const float* __restrict__ bias, void* __restrict__ out,
                      int Lrows)
{
    __shared__ unsigned sA[2][GBM * KSTR];
    __shared__ unsigned sB[2][GBN * KSTR];

    const int tid  = threadIdx.x;
    const int bm   = blockIdx.y * GBM;
    const int bn   = blockIdx.x * GBN;
    const int wid  = tid >> 5;
    const int lane = tid & 31;
    const int wm   = (wid & 1) * 64;
    const int wn   = (wid >> 1) * 32;
    const int qr   = lane >> 2;
    const int ql   = lane & 3;

    const int lrow  = tid >> 2;
    const int lcol4 = (tid & 3) * 4;

    float acc[4][4][4];
#pragma unroll
    for (int i = 0; i < 4; i++)
#pragma unroll
        for (int j = 0; j < 4; j++)
#pragma unroll
            for (int r = 0; r < 4; r++) acc[i][j][r] = 0.f;

    const int NK = C_DIM / GBK;  // 64

    gemm_load_stage(sA[0], sB[0], X, W, bm, bn, 0, lrow, lcol4);

    for (int kt = 0; kt < NK; kt++) {
        const int buf = kt & 1;
        if (kt + 1 < NK) {
            gemm_load_stage(sA[buf ^ 1], sB[buf ^ 1], X, W, bm, bn, (kt + 1) * GBK, lrow, lcol4);
            cp_wait<1>();
        } else {
            cp_wait<0>();
        }
        __syncthreads();

#pragma unroll
        for (int ks = 0; ks < 2; ks++) {
            const int kb = ks * 8;
            unsigned af[4][4], bf[4][2];
#pragma unroll
            for (int mi = 0; mi < 4; mi++) {
                int r0 = wm + mi * 16 + qr;
                af[mi][0] = sA[buf][(r0)     * KSTR + kb + ql];
                af[mi][1] = sA[buf][(r0 + 8) * KSTR + kb + ql];
                af[mi][2] = sA[buf][(r0)     * KSTR + kb + ql + 4];
                af[mi][3] = sA[buf][(r0 + 8) * KSTR + kb + ql + 4];
            }
#pragma unroll
            for (int ni = 0; ni < 4; ni++) {
                int c0 = wn + ni * 8 + qr;
                bf[ni][0] = sB[buf][c0 * KSTR + kb + ql];
                bf[ni][1] = sB[buf][c0 * KSTR + kb + ql + 4];
            }
#pragma unroll
            for (int mi = 0; mi < 4; mi++)
#pragma unroll
                for (int ni = 0; ni < 4; ni++)
                    mma_tf32(acc[mi][ni], af[mi], bf[ni]);
        }
        __syncthreads();
    }

    // Epilogue
#pragma unroll
    for (int mi = 0; mi < 4; mi++) {
#pragma unroll
        for (int ni = 0; ni < 4; ni++) {
            const int m0 = bm + wm + mi * 16 + qr;
            const int n0 = bn + wn + ni * 8 + 2 * ql;
            const float b0 = bias[n0], b1 = bias[n0 + 1];
            const float v00 = acc[mi][ni][0] + b0;
            const float v01 = acc[mi][ni][1] + b1;
            const float v10 = acc[mi][ni][2] + b0;
            const float v11 = acc[mi][ni][3] + b1;
            if (HEADSPLIT) {
                unsigned* op = (unsigned*)out;
                const int bz = m0 / Lrows;
                const int l  = m0 - bz * Lrows;
                const int h  = n0 >> 6;
                const int d  = n0 & 63;
                size_t base = (((size_t)(bz * H_HEADS + h) * Lrows) + l) * D_HEAD + d;
                op[base]     = f2tf(v00);
                op[base + 1] = f2tf(v01);
                const int bz2 = (m0 + 8) / Lrows;
                const int l2  = (m0 + 8) - bz2 * Lrows;
                size_t base2 = (((size_t)(bz2 * H_HEADS + h) * Lrows) + l2) * D_HEAD + d;
                op[base2]     = f2tf(v10);
                op[base2 + 1] = f2tf(v11);
            } else {
                float* op = (float*)out;
                op[(size_t)m0 * C_DIM + n0]           = v00;
                op[(size_t)m0 * C_DIM + n0 + 1]       = v01;
                op[(size_t)(m0 + 8) * C_DIM + n0]     = v10;
                op[(size_t)(m0 + 8) * C_DIM + n0 + 1] = v11;
            }
        }
    }
}

// ---------------------------------------------------------------------------
// Flash attention. All operands are tf32 bits in gmem -> cp.async lands them
// MMA-ready (no cvt passes). P never round-trips through smem: the S
// C-fragments feed the PV MMA directly as A-fragments, with V rows stored
// interleave-permuted so C-frag columns {2ql,2ql+1} align with A-frag key
// slots {ql,ql+4}. 2 CTAs/SM, split K/V cp.async pipeline, log2-domain softmax.
// ---------------------------------------------------------------------------
#define QT 128
#define KCH 64
#define SQ_STR 68   // conflict-free [row][k] fragment reads
#define SV_STR 72   // conflict-free [k][n] fragment reads

#define FLASH_SMEM_WORDS (QT * SQ_STR + KCH * SQ_STR + KCH * SV_STR + KCH)
#define FLASH_SMEM_BYTES (FLASH_SMEM_WORDS * 4)   // 70,912 B (x2 CTAs = 141.8 KB)

#define LOG2E 1.4426950408889634f

// Interleave permutation for V rows within each 8-row group:
// physical slot for logical row j:  j even -> j/2,  j odd -> j/2 + 4.
__device__ __forceinline__ int v_perm_row(int row) {
    int j = row & 7;
    return (row & ~7) + ((j & 1) ? (j >> 1) + 4 : (j >> 1));
}

__global__ __launch_bounds__(256, 2)
void flash_kernel(const float* __restrict__ biasAll)
{
    extern __shared__ unsigned smu[];
    unsigned* uQ    = smu;                    // [QT][SQ_STR] tf32 bits
    unsigned* uK    = uQ + QT * SQ_STR;       // [KCH][SQ_STR]
    unsigned* uV    = uK + KCH * SQ_STR;      // [KCH][SV_STR] (row-permuted)
    float*    fBias = (float*)(uV + KCH * SV_STR);  // [KCH]

    const int tid  = threadIdx.x;
    const int w    = tid >> 5;
    const int lane = tid & 31;
    const int qr   = lane >> 2;
    const int ql   = lane & 3;
    const int q0   = blockIdx.x * QT;
    const int h    = blockIdx.y;
    const int b    = blockIdx.z;

    const unsigned* qp = g_q + (size_t)(b * H_HEADS + h) * LQ * D_HEAD;
    const unsigned* kp = g_k + (size_t)(b * H_HEADS + h) * LK * D_HEAD;
    const unsigned* vp = g_v + (size_t)(b * H_HEADS + h) * LK * D_HEAD;
    const float*    bp = biasAll + (size_t)b * LK;

    // ---- prologue: group A = Q + K0 + bias0, group B = V0 ----
#pragma unroll
    for (int it = 0; it < 8; it++) {
        int f = tid + it * 256;
        int row = f >> 4;
        int c4  = (f & 15) * 4;
        cp_async16(&uQ[row * SQ_STR + c4], &qp[(size_t)(q0 + row) * D_HEAD + c4]);
    }
#pragma unroll
    for (int it = 0; it < 4; it++) {
        int f = tid + it * 256;
        int row = f >> 4;
        int c4  = (f & 15) * 4;
        cp_async16(&uK[row * SQ_STR + c4], &kp[(size_t)row * D_HEAD + c4]);
    }
    if (tid < 16) cp_async16(&fBias[tid * 4], &bp[tid * 4]);
    cp_commit();
#pragma unroll
    for (int it = 0; it < 4; it++) {
        int f = tid + it * 256;
        int row = f >> 4;
        int c4  = (f & 15) * 4;
        cp_async16(&uV[v_perm_row(row) * SV_STR + c4], &vp[(size_t)row * D_HEAD + c4]);
    }
    cp_commit();

    float o[8][4];
#pragma unroll
    for (int ni = 0; ni < 8; ni++)
#pragma unroll
        for (int r = 0; r < 4; r++) o[ni][r] = 0.f;

    float row_m[2] = {-1e30f, -1e30f};   // log2-domain running max
    float row_l[2] = {0.f, 0.f};
    const float scl = 0.125f * LOG2E;    // (1/sqrt(64)) * log2(e)
    const int r0 = w * 16 + qr;

    const int NCH = LK / KCH;  // 64
    for (int i = 0; i < NCH; i++) {
        const int kc0 = i * KCH;

        // ---- K_i (+Q on i==0) arrived ----
        cp_wait<1>();
        if (tid < 16) {   // scale bias to log2 domain in place
            float4 bv = *(float4*)&fBias[tid * 4];
            bv.x *= LOG2E; bv.y *= LOG2E; bv.z *= LOG2E; bv.w *= LOG2E;
            *(float4*)&fBias[tid * 4] = bv;
        }
        __syncthreads();   // #1: K + bias visible to all warps

        // ---- S = Q @ K^T ----
        float s[8][4];
#pragma unroll
        for (int ni = 0; ni < 8; ni++)
#pragma unroll
            for (int r = 0; r < 4; r++) s[ni][r] = 0.f;

#pragma unroll
        for (int kk = 0; kk < 8; kk++) {
            const int kb = kk * 8;
            unsigned af[4];
            af[0] = uQ[(r0)     * SQ_STR + kb + ql];
            af[1] = uQ[(r0 + 8) * SQ_STR + kb + ql];
            af[2] = uQ[(r0)     * SQ_STR + kb + ql + 4];
            af[3] = uQ[(r0 + 8) * SQ_STR + kb + ql + 4];
#pragma unroll
            for (int ni = 0; ni < 8; ni++) {
                unsigned bf[2];
                const int nc = ni * 8 + qr;
                bf[0] = uK[nc * SQ_STR + kb + ql];
                bf[1] = uK[nc * SQ_STR + kb + ql + 4];
                mma_tf32(s[ni], af, bf);
            }
        }

        // scale + per-key bias (log2 domain)
#pragma unroll
        for (int ni = 0; ni < 8; ni++) {
            const int c0 = ni * 8 + 2 * ql;
            const float b0 = fBias[c0], b1 = fBias[c0 + 1];
            s[ni][0] = fmaf(s[ni][0], scl, b0);
            s[ni][1] = fmaf(s[ni][1], scl, b1);
            s[ni][2] = fmaf(s[ni][2], scl, b0);
            s[ni][3] = fmaf(s[ni][3], scl, b1);
        }
        __syncthreads();   // #2: all warps done with K + bias

        // ---- prefetch K(i+1) (+bias) while softmax runs ----
        if (i + 1 < NCH) {
#pragma unroll
            for (int it = 0; it < 4; it++) {
                int f = tid + it * 256;
                int row = f >> 4;
                int c4  = (f & 15) * 4;
                cp_async16(&uK[row * SQ_STR + c4],
                           &kp[(size_t)(kc0 + KCH + row) * D_HEAD + c4]);
            }
            if (tid < 16) cp_async16(&fBias[tid * 4], &bp[kc0 + KCH + tid * 4]);
            cp_commit();
        }

        // ---- online softmax (rows r0, r0+8); quad shfl reductions ----
#pragma unroll
        for (int half = 0; half < 2; half++) {
            float mx = -1e30f;
#pragma unroll
            for (int ni = 0; ni < 8; ni++)
                mx = fmaxf(mx, fmaxf(s[ni][2 * half], s[ni][2 * half + 1]));
            mx = fmaxf(mx, __shfl_xor_sync(0xffffffffu, mx, 1));
            mx = fmaxf(mx, __shfl_xor_sync(0xffffffffu, mx, 2));
            const float mnew  = fmaxf(row_m[half], mx);
            const float alpha = ex2f(row_m[half] - mnew);
            row_m[half] = mnew;
            float ls = 0.f;
#pragma unroll
            for (int ni = 0; ni < 8; ni++) {
                float e0 = ex2f(s[ni][2 * half]     - mnew);
                float e1 = ex2f(s[ni][2 * half + 1] - mnew);
                s[ni][2 * half]     = e0;
                s[ni][2 * half + 1] = e1;
                ls += e0 + e1;
            }
            ls += __shfl_xor_sync(0xffffffffu, ls, 1);
            ls += __shfl_xor_sync(0xffffffffu, ls, 2);
            row_l[half] = row_l[half] * alpha + ls;
#pragma unroll
            for (int ni = 0; ni < 8; ni++) {
                o[ni][2 * half]     *= alpha;
                o[ni][2 * half + 1] *= alpha;
            }
        }

        // ---- V_i arrived ----
        if (i + 1 < NCH) cp_wait<1>(); else cp_wait<0>();
        __syncthreads();   // #3: V visible to all warps

        // ---- O += P @ V : S C-fragments reused directly as A-fragments ----
        // a-frag (qr,ql) interprets keys {kb+ql, kb+ql+4}; permuted V storage
        // makes physical rows {ql, ql+4} hold logical keys {2ql, 2ql+1},
        // matching C-frag columns (s0,s2,s1,s3 ordering).
#pragma unroll
        for (int kk = 0; kk < 8; kk++) {
            const int kb = kk * 8;
            unsigned af[4];
            af[0] = f2tf(s[kk][0]);
            af[1] = f2tf(s[kk][2]);
            af[2] = f2tf(s[kk][1]);
            af[3] = f2tf(s[kk][3]);
#pragma unroll
            for (int ni = 0; ni < 8; ni++) {
                unsigned bf[2];
                const int nc = ni * 8 + qr;
                bf[0] = uV[(kb + ql)     * SV_STR + nc];
                bf[1] = uV[(kb + ql + 4) * SV_STR + nc];
                mma_tf32(o[ni], af, bf);
            }
        }
        __syncthreads();   // #4: all warps done with V

        // ---- prefetch V(i+1) (permuted rows) ----
        if (i + 1 < NCH) {
#pragma unroll
            for (int it = 0; it < 4; it++) {
                int f = tid + it * 256;
                int row = f >> 4;
                int c4  = (f & 15) * 4;
                cp_async16(&uV[v_perm_row(row) * SV_STR + c4],
                           &vp[(size_t)(kc0 + KCH + row) * D_HEAD + c4]);
            }
            cp_commit();
        }
    }

    // ---- normalize and write context as tf32 bits [B, Lq, C] ----
    const float inv0 = __fdividef(1.f, row_l[0]);
    const float inv1 = __fdividef(1.f, row_l[1]);
    unsigned* ctx = g_ctx + (size_t)b * LQ * C_DIM;
    const int rA = q0 + r0;
#pragma unroll
    for (int ni = 0; ni < 8; ni++) {
        const int col = h * 64 + ni * 8 + 2 * ql;
        uint2 c0, c1;
        c0.x = f2tf(o[ni][0] * inv0);
        c0.y = f2tf(o[ni][1] * inv0);
        c1.x = f2tf(o[ni][2] * inv1);
        c1.y = f2tf(o[ni][3] * inv1);
        *(uint2*)&ctx[(size_t)rA * C_DIM + col]       = c0;
        *(uint2*)&ctx[(size_t)(rA + 8) * C_DIM + col] = c1;
    }
}

// ---------------------------------------------------------------------------
// kernel_launch: 6 stream-ordered launches (graph-capturable, alloc-free)
// ---------------------------------------------------------------------------
extern "C" void kernel_launch(void* const* d_in, const int* in_sizes, int n_in,
                              void* d_out, int out_size)
{
    const float* Q      = (const float*)d_in[0];
    const float* K_in   = (const float*)d_in[1];
    const float* V_in   = (const float*)d_in[2];
    const float* V_bias = (const float*)d_in[3];
    const float* Wq_b   = (const float*)d_in[5];
    const float* Wk_b   = (const float*)d_in[7];
    const float* Wv_b   = (const float*)d_in[9];
    const float* Wo_b   = (const float*)d_in[11];

    unsigned *qptr = nullptr, *kptr = nullptr, *vptr = nullptr, *ctxptr = nullptr;
    unsigned *xq = nullptr, *xk = nullptr, *xv = nullptr, *wt = nullptr;
    cudaGetSymbolAddress((void**)&qptr,   g_q);
    cudaGetSymbolAddress((void**)&kptr,   g_k);
    cudaGetSymbolAddress((void**)&vptr,   g_v);
    cudaGetSymbolAddress((void**)&ctxptr, g_ctx);
    cudaGetSymbolAddress((void**)&xq,     g_xq);
    cudaGetSymbolAddress((void**)&xk,     g_xk);
    cudaGetSymbolAddress((void**)&xv,     g_xv);
    cudaGetSymbolAddress((void**)&wt,     g_wt);

    cudaFuncSetAttribute(flash_kernel,
                         cudaFuncAttributeMaxDynamicSharedMemorySize,
                         FLASH_SMEM_BYTES);

    // Pre-convert X inputs and weights to tf32 bits (single fused pass).
    precvt_kernel<<<1184, 512>>>((const float4*)Q, (const float4*)K_in,
                                 (const float4*)V_in, (const float4*)d_in[4],
                                 (const float4*)d_in[6], (const float4*)d_in[8],
                                 (const float4*)d_in[10]);

    // Projections (tf32-in, tf32 head-split out)
    gemm_tf32_kernel<1><<<dim3(C_DIM / GBN, (B_BATCH * LQ) / GBM), 256>>>(
        xq, wt + 0 * C_DIM * C_DIM, Wq_b, qptr, LQ);
    gemm_tf32_kernel<1><<<dim3(C_DIM / GBN, (B_BATCH * LK) / GBM), 256>>>(
        xk, wt + 1 * C_DIM * C_DIM, Wk_b, kptr, LK);
    gemm_tf32_kernel<1><<<dim3(C_DIM / GBN, (B_BATCH * LK) / GBM), 256>>>(
        xv, wt + 2 * C_DIM * C_DIM, Wv_b, vptr, LK);

    // Attention
    flash_kernel<<<dim3(LQ / QT, H_HEADS, B_BATCH), 256, FLASH_SMEM_BYTES>>>(V_bias);

    // Output projection: ctx (tf32 bits) @ Wo^T + b -> fp32 d_out
    gemm_tf32_kernel<0><<<dim3(C_DIM / GBN, (B_BATCH * LQ) / GBM), 256>>>(
        ctxptr, wt + 3 * C_DIM * C_DIM, Wo_b, d_out, 1);
}

// round 6
// speedup vs baseline: 1.2677x; 1.0260x over previous
#include <cuda_runtime.h>
#include <cstdint>
#include <cstddef>

// ---------------------------------------------------------------------------
// Problem constants
// ---------------------------------------------------------------------------
#define C_DIM   1024
#define H_HEADS 16
#define D_HEAD  64
#define B_BATCH 2
#define LQ      1024
#define LK      4096

// ---------------------------------------------------------------------------
// Device scratch (allocation-free: __device__ globals). All tf32 bit patterns.
// g_x* / g_wt / g_ctx are k-PERMUTED along their last dim (8-groups: k<4->2k,
// k>=4 -> 2(k-4)+1) so GEMM fragment pairs (k, k+4) are adjacent -> LDS.64.
// g_q/g_k/g_v are plain layout (flash consumes them unpermuted).
// ---------------------------------------------------------------------------
__device__ unsigned g_q[B_BATCH * H_HEADS * LQ * D_HEAD];   //  8 MB [B,H,Lq,D]
__device__ unsigned g_k[B_BATCH * H_HEADS * LK * D_HEAD];   // 32 MB [B,H,Lk,D]
__device__ unsigned g_v[B_BATCH * H_HEADS * LK * D_HEAD];   // 32 MB [B,H,Lk,D]
__device__ unsigned g_ctx[B_BATCH * LQ * C_DIM];            //  8 MB [B,Lq,C] (perm)
__device__ unsigned g_xq[B_BATCH * LQ * C_DIM];             //  8 MB  pre-cvt Q (perm)
__device__ unsigned g_xk[B_BATCH * LK * C_DIM];             // 32 MB  pre-cvt K_in (perm)
__device__ unsigned g_xv[B_BATCH * LK * C_DIM];             // 32 MB  pre-cvt V_in (perm)
__device__ unsigned g_wt[4 * C_DIM * C_DIM];                // 16 MB  pre-cvt W (perm)

// ---------------------------------------------------------------------------
// Helpers
// ---------------------------------------------------------------------------
__device__ __forceinline__ unsigned f2tf(float f) {
    unsigned u;
    asm volatile("cvt.rna.tf32.f32 %0, %1;" : "=r"(u) : "f"(f));
    return u;
}
__device__ __forceinline__ float ex2f(float x) {
    float y;
    asm volatile("ex2.approx.f32 %0, %1;" : "=f"(y) : "f"(x));
    return y;
}
// within-8-group k permutation (applies to full index)
__device__ __forceinline__ int kperm8(int k) {
    int j = k & 7;
    return (k & ~7) + ((j < 4) ? (2 * j) : (2 * (j - 4) + 1));
}

// D = A(row-major m16 x k8) * B(col-major k8 x n8) + D  (tf32, fp32 accum)
__device__ __forceinline__ void mma_tf32(float c[4], const unsigned a[4], const unsigned b[2]) {
    asm volatile(
        "mma.sync.aligned.m16n8k8.row.col.f32.tf32.tf32.f32 "
        "{%0,%1,%2,%3}, {%4,%5,%6,%7}, {%8,%9}, {%0,%1,%2,%3};"
        : "+f"(c[0]), "+f"(c[1]), "+f"(c[2]), "+f"(c[3])
        : "r"(a[0]), "r"(a[1]), "r"(a[2]), "r"(a[3]), "r"(b[0]), "r"(b[1]));
}

__device__ __forceinline__ void cp_async16(void* smem, const void* gmem) {
    unsigned sa = (unsigned)__cvta_generic_to_shared(smem);
    asm volatile("cp.async.ca.shared.global [%0], [%1], 16;" :: "r"(sa), "l"(gmem));
}
__device__ __forceinline__ void cp_commit() { asm volatile("cp.async.commit_group;"); }
template <int N>
__device__ __forceinline__ void cp_wait() { asm volatile("cp.async.wait_group %0;" :: "n"(N)); }

// ---------------------------------------------------------------------------
// Pre-convert pass: fp32 -> tf32 bits, k-PERMUTED scatter within 8-groups.
// Every matrix here has last dim 1024 (multiple of 8), so flat%8 == k%8.
// ---------------------------------------------------------------------------
#define N4_Q  (B_BATCH * LQ * C_DIM / 4)   // 524288
#define N4_K  (B_BATCH * LK * C_DIM / 4)   // 2097152
#define N4_W  (C_DIM * C_DIM / 4)          // 262144

__global__ __launch_bounds__(512)
void precvt_kernel(const float4* __restrict__ Q, const float4* __restrict__ K,
                   const float4* __restrict__ V, const float4* __restrict__ Wq,
                   const float4* __restrict__ Wk, const float4* __restrict__ Wv,
                   const float4* __restrict__ Wo)
{
    const int total = N4_Q + 2 * N4_K + 4 * N4_W;
    for (int i = blockIdx.x * blockDim.x + threadIdx.x; i < total;
         i += gridDim.x * blockDim.x) {
        const float4* s;
        unsigned* d;
        int j = i;
        if (j < N4_Q)                { s = Q; d = g_xq; }
        else if ((j -= N4_Q) < N4_K) { s = K; d = g_xk; }
        else if ((j -= N4_K) < N4_K) { s = V; d = g_xv; }
        else {
            j -= N4_K;
            int w = j / N4_W;
            j -= w * N4_W;
            s = (w == 0) ? Wq : (w == 1) ? Wk : (w == 2) ? Wv : Wo;
            d = g_wt + (size_t)w * (C_DIM * C_DIM);
        }
        float4 v = s[j];
        // elements j*4..j*4+3 are k-consecutive; scatter into permuted slots
        int e     = j * 4;
        int base  = e & ~7;
        int start = (e & 4) ? 1 : 0;   // low half -> even slots, high -> odd
        d[base + start]     = f2tf(v.x);
        d[base + start + 2] = f2tf(v.y);
        d[base + start + 4] = f2tf(v.z);
        d[base + start + 6] = f2tf(v.w);
    }
}

// ---------------------------------------------------------------------------
// TF32 GEMM:  out[m,n] = sum_k X[m,k] * W[n,k] + bias[n]
//   X, W are tf32 bits in k-permuted layout -> fragment pairs adjacent.
//   3-stage cp.async ring, one __syncthreads per k-tile, LDS.64 frag loads.
//   HEADSPLIT==1: scatter tf32 bits to [B,H,Lrows,D] (plain layout).
//   HEADSPLIT==0: fp32 [M,C] plain layout.
// BM=128, BN=128, BK=16, 256 threads (8 warps, 2x4), warp tile 64x32.
// ---------------------------------------------------------------------------
#define GBM 128
#define GBN 128
#define GBK 16
#define KSTR 24          // row stride: qr rows land on disjoint bank groups
#define GSTAGE_WORDS (GBM * KSTR)                 // 3072 words per matrix
#define GEMM_SMEM_BYTES (3 * 2 * GSTAGE_WORDS * 4)  // 73,728 B (x2 CTAs OK)

__device__ __forceinline__ void gemm_load_stage(
    unsigned* sA, unsigned* sB, const unsigned* __restrict__ X,
    const unsigned* __restrict__ W, int bm, int bn, int k0, int lrow, int lcol4)
{
#pragma unroll
    for (int p = 0; p < 2; p++) {
        int row = lrow + p * 64;
        cp_async16(&sA[row * KSTR + lcol4], &X[(size_t)(bm + row) * C_DIM + k0 + lcol4]);
        cp_async16(&sB[row * KSTR + lcol4], &W[(size_t)(bn + row) * C_DIM + k0 + lcol4]);
    }
    cp_commit();
}

template <int HEADSPLIT>
__global__ __launch_bounds__(256, 2)
void gemm_tf32_kernel(const unsigned* __restrict__ X, const unsigned* __restrict__ W,
                      const float* __restrict__ bias, void* __restrict__ out,
                      int Lrows)
{
    extern __shared__ unsigned gsm[];
    unsigned* sAr = gsm;                       // [3][GSTAGE_WORDS]
    unsigned* sBr = gsm + 3 * GSTAGE_WORDS;    // [3][GSTAGE_WORDS]

    const int tid  = threadIdx.x;
    const int bm   = blockIdx.y * GBM;
    const int bn   = blockIdx.x * GBN;
    const int wid  = tid >> 5;
    const int lane = tid & 31;
    const int wm   = (wid & 1) * 64;
    const int wn   = (wid >> 1) * 32;
    const int qr   = lane >> 2;
    const int ql   = lane & 3;

    const int lrow  = tid >> 2;
    const int lcol4 = (tid & 3) * 4;

    float acc[4][4][4];
#pragma unroll
    for (int i = 0; i < 4; i++)
#pragma unroll
        for (int j = 0; j < 4; j++)
#pragma unroll
            for (int r = 0; r < 4; r++) acc[i][j][r] = 0.f;

    const int NK = C_DIM / GBK;  // 64

    gemm_load_stage(sAr, sBr, X, W, bm, bn, 0, lrow, lcol4);
    gemm_load_stage(sAr + GSTAGE_WORDS, sBr + GSTAGE_WORDS, X, W, bm, bn, GBK, lrow, lcol4);

    for (int kt = 0; kt < NK; kt++) {
        if (kt + 1 < NK) cp_wait<1>(); else cp_wait<0>();
        __syncthreads();

        const int buf = kt % 3;
        if (kt + 2 < NK) {
            const int nb = (kt + 2) % 3;
            gemm_load_stage(sAr + nb * GSTAGE_WORDS, sBr + nb * GSTAGE_WORDS,
                            X, W, bm, bn, (kt + 2) * GBK, lrow, lcol4);
        }

        const unsigned* sA = sAr + buf * GSTAGE_WORDS;
        const unsigned* sB = sBr + buf * GSTAGE_WORDS;

#pragma unroll
        for (int ks = 0; ks < 2; ks++) {
            const int kb = ks * 8;          // permuted-slot group base
            unsigned af[4][4], bf[4][2];
#pragma unroll
            for (int mi = 0; mi < 4; mi++) {
                int r0 = wm + mi * 16 + qr;
                uint2 lo = *(const uint2*)&sA[(r0)     * KSTR + kb + 2 * ql];
                uint2 hi = *(const uint2*)&sA[(r0 + 8) * KSTR + kb + 2 * ql];
                af[mi][0] = lo.x;   // k = ql
                af[mi][1] = hi.x;
                af[mi][2] = lo.y;   // k = ql+4
                af[mi][3] = hi.y;
            }
#pragma unroll
            for (int ni = 0; ni < 4; ni++) {
                int c0 = wn + ni * 8 + qr;
                uint2 bb = *(const uint2*)&sB[c0 * KSTR + kb + 2 * ql];
                bf[ni][0] = bb.x;
                bf[ni][1] = bb.y;
            }
#pragma unroll
            for (int mi = 0; mi < 4; mi++)
#pragma unroll
                for (int ni = 0; ni < 4; ni++)
                    mma_tf32(acc[mi][ni], af[mi], bf[ni]);
        }
    }

    // Epilogue (plain layouts)
#pragma unroll
    for (int mi = 0; mi < 4; mi++) {
#pragma unroll
        for (int ni = 0; ni < 4; ni++) {
            const int m0 = bm + wm + mi * 16 + qr;
            const int n0 = bn + wn + ni * 8 + 2 * ql;
            const float b0 = bias[n0], b1 = bias[n0 + 1];
            const float v00 = acc[mi][ni][0] + b0;
            const float v01 = acc[mi][ni][1] + b1;
            const float v10 = acc[mi][ni][2] + b0;
            const float v11 = acc[mi][ni][3] + b1;
            if (HEADSPLIT) {
                unsigned* op = (unsigned*)out;
                const int bz = m0 / Lrows;
                const int l  = m0 - bz * Lrows;
                const int h  = n0 >> 6;
                const int d  = n0 & 63;
                size_t base = (((size_t)(bz * H_HEADS + h) * Lrows) + l) * D_HEAD + d;
                op[base]     = f2tf(v00);
                op[base + 1] = f2tf(v01);
                const int bz2 = (m0 + 8) / Lrows;
                const int l2  = (m0 + 8) - bz2 * Lrows;
                size_t base2 = (((size_t)(bz2 * H_HEADS + h) * Lrows) + l2) * D_HEAD + d;
                op[base2]     = f2tf(v10);
                op[base2 + 1] = f2tf(v11);
            } else {
                float* op = (float*)out;
                op[(size_t)m0 * C_DIM + n0]           = v00;
                op[(size_t)m0 * C_DIM + n0 + 1]       = v01;
                op[(size_t)(m0 + 8) * C_DIM + n0]     = v10;
                op[(size_t)(m0 + 8) * C_DIM + n0 + 1] = v11;
            }
        }
    }
}

// ---------------------------------------------------------------------------
// Flash attention. Identical to R5 (tf32 operands land MMA-ready via cp.async;
// S C-fragments feed PV directly with row-permuted V). Only change: the ctx
// epilogue writes the O-projection's k-PERMUTED layout.
// ---------------------------------------------------------------------------
#define QT 128
#define KCH 64
#define SQ_STR 68
#define SV_STR 72

#define FLASH_SMEM_WORDS (QT * SQ_STR + KCH * SQ_STR + KCH * SV_STR + KCH)
#define FLASH_SMEM_BYTES (FLASH_SMEM_WORDS * 4)   // 70,912 B (x2 CTAs)

#define LOG2E 1.4426950408889634f

__device__ __forceinline__ int v_perm_row(int row) {
    int j = row & 7;
    return (row & ~7) + ((j & 1) ? (j >> 1) + 4 : (j >> 1));
}

__global__ __launch_bounds__(256, 2)
void flash_kernel(const float* __restrict__ biasAll)
{
    extern __shared__ unsigned smu[];
    unsigned* uQ    = smu;
    unsigned* uK    = uQ + QT * SQ_STR;
    unsigned* uV    = uK + KCH * SQ_STR;
    float*    fBias = (float*)(uV + KCH * SV_STR);

    const int tid  = threadIdx.x;
    const int w    = tid >> 5;
    const int lane = tid & 31;
    const int qr   = lane >> 2;
    const int ql   = lane & 3;
    const int q0   = blockIdx.x * QT;
    const int h    = blockIdx.y;
    const int b    = blockIdx.z;

    const unsigned* qp = g_q + (size_t)(b * H_HEADS + h) * LQ * D_HEAD;
    const unsigned* kp = g_k + (size_t)(b * H_HEADS + h) * LK * D_HEAD;
    const unsigned* vp = g_v + (size_t)(b * H_HEADS + h) * LK * D_HEAD;
    const float*    bp = biasAll + (size_t)b * LK;

    // ---- prologue: group A = Q + K0 + bias0, group B = V0 ----
#pragma unroll
    for (int it = 0; it < 8; it++) {
        int f = tid + it * 256;
        int row = f >> 4;
        int c4  = (f & 15) * 4;
        cp_async16(&uQ[row * SQ_STR + c4], &qp[(size_t)(q0 + row) * D_HEAD + c4]);
    }
#pragma unroll
    for (int it = 0; it < 4; it++) {
        int f = tid + it * 256;
        int row = f >> 4;
        int c4  = (f & 15) * 4;
        cp_async16(&uK[row * SQ_STR + c4], &kp[(size_t)row * D_HEAD + c4]);
    }
    if (tid < 16) cp_async16(&fBias[tid * 4], &bp[tid * 4]);
    cp_commit();
#pragma unroll
    for (int it = 0; it < 4; it++) {
        int f = tid + it * 256;
        int row = f >> 4;
        int c4  = (f & 15) * 4;
        cp_async16(&uV[v_perm_row(row) * SV_STR + c4], &vp[(size_t)row * D_HEAD + c4]);
    }
    cp_commit();

    float o[8][4];
#pragma unroll
    for (int ni = 0; ni < 8; ni++)
#pragma unroll
        for (int r = 0; r < 4; r++) o[ni][r] = 0.f;

    float row_m[2] = {-1e30f, -1e30f};
    float row_l[2] = {0.f, 0.f};
    const float scl = 0.125f * LOG2E;
    const int r0 = w * 16 + qr;

    const int NCH = LK / KCH;  // 64
    for (int i = 0; i < NCH; i++) {
        const int kc0 = i * KCH;

        cp_wait<1>();
        if (tid < 16) {
            float4 bv = *(float4*)&fBias[tid * 4];
            bv.x *= LOG2E; bv.y *= LOG2E; bv.z *= LOG2E; bv.w *= LOG2E;
            *(float4*)&fBias[tid * 4] = bv;
        }
        __syncthreads();   // #1: K + bias visible

        // ---- S = Q @ K^T ----
        float s[8][4];
#pragma unroll
        for (int ni = 0; ni < 8; ni++)
#pragma unroll
            for (int r = 0; r < 4; r++) s[ni][r] = 0.f;

#pragma unroll
        for (int kk = 0; kk < 8; kk++) {
            const int kb = kk * 8;
            unsigned af[4];
            af[0] = uQ[(r0)     * SQ_STR + kb + ql];
            af[1] = uQ[(r0 + 8) * SQ_STR + kb + ql];
            af[2] = uQ[(r0)     * SQ_STR + kb + ql + 4];
            af[3] = uQ[(r0 + 8) * SQ_STR + kb + ql + 4];
#pragma unroll
            for (int ni = 0; ni < 8; ni++) {
                unsigned bf[2];
                const int nc = ni * 8 + qr;
                bf[0] = uK[nc * SQ_STR + kb + ql];
                bf[1] = uK[nc * SQ_STR + kb + ql + 4];
                mma_tf32(s[ni], af, bf);
            }
        }

#pragma unroll
        for (int ni = 0; ni < 8; ni++) {
            const int c0 = ni * 8 + 2 * ql;
            const float b0 = fBias[c0], b1 = fBias[c0 + 1];
            s[ni][0] = fmaf(s[ni][0], scl, b0);
            s[ni][1] = fmaf(s[ni][1], scl, b1);
            s[ni][2] = fmaf(s[ni][2], scl, b0);
            s[ni][3] = fmaf(s[ni][3], scl, b1);
        }
        __syncthreads();   // #2: done with K + bias

        if (i + 1 < NCH) {
#pragma unroll
            for (int it = 0; it < 4; it++) {
                int f = tid + it * 256;
                int row = f >> 4;
                int c4  = (f & 15) * 4;
                cp_async16(&uK[row * SQ_STR + c4],
                           &kp[(size_t)(kc0 + KCH + row) * D_HEAD + c4]);
            }
            if (tid < 16) cp_async16(&fBias[tid * 4], &bp[kc0 + KCH + tid * 4]);
            cp_commit();
        }

        // ---- online softmax ----
#pragma unroll
        for (int half = 0; half < 2; half++) {
            float mx = -1e30f;
#pragma unroll
            for (int ni = 0; ni < 8; ni++)
                mx = fmaxf(mx, fmaxf(s[ni][2 * half], s[ni][2 * half + 1]));
            mx = fmaxf(mx, __shfl_xor_sync(0xffffffffu, mx, 1));
            mx = fmaxf(mx, __shfl_xor_sync(0xffffffffu, mx, 2));
            const float mnew  = fmaxf(row_m[half], mx);
            const float alpha = ex2f(row_m[half] - mnew);
            row_m[half] = mnew;
            float ls = 0.f;
#pragma unroll
            for (int ni = 0; ni < 8; ni++) {
                float e0 = ex2f(s[ni][2 * half]     - mnew);
                float e1 = ex2f(s[ni][2 * half + 1] - mnew);
                s[ni][2 * half]     = e0;
                s[ni][2 * half + 1] = e1;
                ls += e0 + e1;
            }
            ls += __shfl_xor_sync(0xffffffffu, ls, 1);
            ls += __shfl_xor_sync(0xffffffffu, ls, 2);
            row_l[half] = row_l[half] * alpha + ls;
#pragma unroll
            for (int ni = 0; ni < 8; ni++) {
                o[ni][2 * half]     *= alpha;
                o[ni][2 * half + 1] *= alpha;
            }
        }

        if (i + 1 < NCH) cp_wait<1>(); else cp_wait<0>();
        __syncthreads();   // #3: V visible

        // ---- O += P @ V (C-frag -> A-frag direct reuse) ----
#pragma unroll
        for (int kk = 0; kk < 8; kk++) {
            const int kb = kk * 8;
            unsigned af[4];
            af[0] = f2tf(s[kk][0]);
            af[1] = f2tf(s[kk][2]);
            af[2] = f2tf(s[kk][1]);
            af[3] = f2tf(s[kk][3]);
#pragma unroll
            for (int ni = 0; ni < 8; ni++) {
                unsigned bf[2];
                const int nc = ni * 8 + qr;
                bf[0] = uV[(kb + ql)     * SV_STR + nc];
                bf[1] = uV[(kb + ql + 4) * SV_STR + nc];
                mma_tf32(o[ni], af, bf);
            }
        }
        __syncthreads();   // #4: done with V

        if (i + 1 < NCH) {
#pragma unroll
            for (int it = 0; it < 4; it++) {
                int f = tid + it * 256;
                int row = f >> 4;
                int c4  = (f & 15) * 4;
                cp_async16(&uV[v_perm_row(row) * SV_STR + c4],
                           &vp[(size_t)(kc0 + KCH + row) * D_HEAD + c4]);
            }
            cp_commit();
        }
    }

    // ---- normalize; write ctx as tf32 bits in k-PERMUTED layout ----
    const float inv0 = __fdividef(1.f, row_l[0]);
    const float inv1 = __fdividef(1.f, row_l[1]);
    unsigned* ctx = g_ctx + (size_t)b * LQ * C_DIM;
    const int rA = q0 + r0;
#pragma unroll
    for (int ni = 0; ni < 8; ni++) {
        const int col = h * 64 + ni * 8 + 2 * ql;
        const int p0 = kperm8(col);
        const int p1 = kperm8(col + 1);
        ctx[(size_t)rA * C_DIM + p0]       = f2tf(o[ni][0] * inv0);
        ctx[(size_t)rA * C_DIM + p1]       = f2tf(o[ni][1] * inv0);
        ctx[(size_t)(rA + 8) * C_DIM + p0] = f2tf(o[ni][2] * inv1);
        ctx[(size_t)(rA + 8) * C_DIM + p1] = f2tf(o[ni][3] * inv1);
    }
}

// ---------------------------------------------------------------------------
// kernel_launch: 6 stream-ordered launches (graph-capturable, alloc-free)
// ---------------------------------------------------------------------------
extern "C" void kernel_launch(void* const* d_in, const int* in_sizes, int n_in,
                              void* d_out, int out_size)
{
    const float* Q      = (const float*)d_in[0];
    const float* K_in   = (const float*)d_in[1];
    const float* V_in   = (const float*)d_in[2];
    const float* V_bias = (const float*)d_in[3];
    const float* Wq_b   = (const float*)d_in[5];
    const float* Wk_b   = (const float*)d_in[7];
    const float* Wv_b   = (const float*)d_in[9];
    const float* Wo_b   = (const float*)d_in[11];

    unsigned *qptr = nullptr, *kptr = nullptr, *vptr = nullptr, *ctxptr = nullptr;
    unsigned *xq = nullptr, *xk = nullptr, *xv = nullptr, *wt = nullptr;
    cudaGetSymbolAddress((void**)&qptr,   g_q);
    cudaGetSymbolAddress((void**)&kptr,   g_k);
    cudaGetSymbolAddress((void**)&vptr,   g_v);
    cudaGetSymbolAddress((void**)&ctxptr, g_ctx);
    cudaGetSymbolAddress((void**)&xq,     g_xq);
    cudaGetSymbolAddress((void**)&xk,     g_xk);
    cudaGetSymbolAddress((void**)&xv,     g_xv);
    cudaGetSymbolAddress((void**)&wt,     g_wt);

    cudaFuncSetAttribute(flash_kernel,
                         cudaFuncAttributeMaxDynamicSharedMemorySize,
                         FLASH_SMEM_BYTES);
    cudaFuncSetAttribute(gemm_tf32_kernel<0>,
                         cudaFuncAttributeMaxDynamicSharedMemorySize,
                         GEMM_SMEM_BYTES);
    cudaFuncSetAttribute(gemm_tf32_kernel<1>,
                         cudaFuncAttributeMaxDynamicSharedMemorySize,
                         GEMM_SMEM_BYTES);

    // Pre-convert X inputs and weights to tf32 bits, k-permuted.
    precvt_kernel<<<1184, 512>>>((const float4*)Q, (const float4*)K_in,
                                 (const float4*)V_in, (const float4*)d_in[4],
                                 (const float4*)d_in[6], (const float4*)d_in[8],
                                 (const float4*)d_in[10]);

    // Projections (permuted tf32 in, plain tf32 head-split out)
    gemm_tf32_kernel<1><<<dim3(C_DIM / GBN, (B_BATCH * LQ) / GBM), 256, GEMM_SMEM_BYTES>>>(
        xq, wt + 0 * C_DIM * C_DIM, Wq_b, qptr, LQ);
    gemm_tf32_kernel<1><<<dim3(C_DIM / GBN, (B_BATCH * LK) / GBM), 256, GEMM_SMEM_BYTES>>>(
        xk, wt + 1 * C_DIM * C_DIM, Wk_b, kptr, LK);
    gemm_tf32_kernel<1><<<dim3(C_DIM / GBN, (B_BATCH * LK) / GBM), 256, GEMM_SMEM_BYTES>>>(
        xv, wt + 2 * C_DIM * C_DIM, Wv_b, vptr, LK);

    // Attention
    flash_kernel<<<dim3(LQ / QT, H_HEADS, B_BATCH), 256, FLASH_SMEM_BYTES>>>(V_bias);

    // Output projection: permuted ctx @ permuted Wo^T + b -> fp32 d_out
    gemm_tf32_kernel<0><<<dim3(C_DIM / GBN, (B_BATCH * LQ) / GBM), 256, GEMM_SMEM_BYTES>>>(
        ctxptr, wt + 3 * C_DIM * C_DIM, Wo_b, d_out, 1);
}

// round 9
// speedup vs baseline: 1.3802x; 1.0887x over previous
#include <cuda_runtime.h>
#include <cstdint>
#include <cstddef>

// ---------------------------------------------------------------------------
// Problem constants
// ---------------------------------------------------------------------------
#define C_DIM   1024
#define H_HEADS 16
#define D_HEAD  64
#define B_BATCH 2
#define LQ      1024
#define LK      4096

// ---------------------------------------------------------------------------
// Device scratch (allocation-free). All tf32 bit patterns.
// g_x*/g_wt/g_ctx: k-PERMUTED last dim (8-groups: k<4 -> slot 2k, k>=4 ->
// slot 2(k-4)+1) so GEMM fragment pairs (k,k+4) are adjacent (LDS.64).
// g_q/g_k: d-PERMUTED (same permutation) for flash's S-loop LDS.64.
// g_v: plain (PV consumes d as the N dimension).
// ---------------------------------------------------------------------------
__device__ unsigned g_q[B_BATCH * H_HEADS * LQ * D_HEAD];
__device__ unsigned g_k[B_BATCH * H_HEADS * LK * D_HEAD];
__device__ unsigned g_v[B_BATCH * H_HEADS * LK * D_HEAD];
__device__ unsigned g_ctx[B_BATCH * LQ * C_DIM];
__device__ unsigned g_xq[B_BATCH * LQ * C_DIM];
__device__ unsigned g_xk[B_BATCH * LK * C_DIM];
__device__ unsigned g_xv[B_BATCH * LK * C_DIM];
__device__ unsigned g_wt[4 * C_DIM * C_DIM];

// ---------------------------------------------------------------------------
// Helpers
// ---------------------------------------------------------------------------
__device__ __forceinline__ unsigned f2tf(float f) {
    unsigned u;
    asm volatile("cvt.rna.tf32.f32 %0, %1;" : "=r"(u) : "f"(f));
    return u;
}
__device__ __forceinline__ float ex2f(float x) {
    float y;
    asm volatile("ex2.approx.f32 %0, %1;" : "=f"(y) : "f"(x));
    return y;
}
__device__ __forceinline__ int kperm8(int k) {
    int j = k & 7;
    return (k & ~7) + ((j < 4) ? (2 * j) : (2 * (j - 4) + 1));
}
__device__ __forceinline__ void mma_tf32(float c[4], const unsigned a[4], const unsigned b[2]) {
    asm volatile(
        "mma.sync.aligned.m16n8k8.row.col.f32.tf32.tf32.f32 "
        "{%0,%1,%2,%3}, {%4,%5,%6,%7}, {%8,%9}, {%0,%1,%2,%3};"
        : "+f"(c[0]), "+f"(c[1]), "+f"(c[2]), "+f"(c[3])
        : "r"(a[0]), "r"(a[1]), "r"(a[2]), "r"(a[3]), "r"(b[0]), "r"(b[1]));
}
__device__ __forceinline__ void cp_async16(void* smem, const void* gmem) {
    unsigned sa = (unsigned)__cvta_generic_to_shared(smem);
    asm volatile("cp.async.ca.shared.global [%0], [%1], 16;" :: "r"(sa), "l"(gmem));
}
__device__ __forceinline__ void cp_commit() { asm volatile("cp.async.commit_group;"); }
template <int N>
__device__ __forceinline__ void cp_wait() { asm volatile("cp.async.wait_group %0;" :: "n"(N)); }

// ---------------------------------------------------------------------------
// Pre-convert pass: fp32 -> tf32 bits, k-permuted scatter
// ---------------------------------------------------------------------------
#define N4_Q  (B_BATCH * LQ * C_DIM / 4)
#define N4_K  (B_BATCH * LK * C_DIM / 4)
#define N4_W  (C_DIM * C_DIM / 4)

__global__ __launch_bounds__(512)
void precvt_kernel(const float4* __restrict__ Q, const float4* __restrict__ K,
                   const float4* __restrict__ V, const float4* __restrict__ Wq,
                   const float4* __restrict__ Wk, const float4* __restrict__ Wv,
                   const float4* __restrict__ Wo)
{
    const int total = N4_Q + 2 * N4_K + 4 * N4_W;
    for (int i = blockIdx.x * blockDim.x + threadIdx.x; i < total;
         i += gridDim.x * blockDim.x) {
        const float4* s;
        unsigned* d;
        int j = i;
        if (j < N4_Q)                { s = Q; d = g_xq; }
        else if ((j -= N4_Q) < N4_K) { s = K; d = g_xk; }
        else if ((j -= N4_K) < N4_K) { s = V; d = g_xv; }
        else {
            j -= N4_K;
            int w = j / N4_W;
            j -= w * N4_W;
            s = (w == 0) ? Wq : (w == 1) ? Wk : (w == 2) ? Wv : Wo;
            d = g_wt + (size_t)w * (C_DIM * C_DIM);
        }
        float4 v = s[j];
        int e     = j * 4;
        int base  = e & ~7;
        int start = (e & 4) ? 1 : 0;
        d[base + start]     = f2tf(v.x);
        d[base + start + 2] = f2tf(v.y);
        d[base + start + 4] = f2tf(v.z);
        d[base + start + 6] = f2tf(v.w);
    }
}

// ---------------------------------------------------------------------------
// TF32 GEMM body: out[m,n] = sum_k X[m,k]*W[n,k] + bias[n]
// k-permuted operands, 3-stage cp.async ring, 1 sync/k-tile, LDS.64 frags.
// HS==1: head-split scatter of tf32 bits (permd: d-permuted for Q/K).
// HS==0: fp32 [M,C] plain.
// BM=BN=128, BK=16, 256 thr (8 warps 2x4), warp tile 64x32, 2 CTAs/SM.
// ---------------------------------------------------------------------------
#define GBM 128
#define GBN 128
#define GBK 16
#define KSTR 24
#define GSTAGE_WORDS (GBM * KSTR)
#define GEMM_SMEM_BYTES (3 * 2 * GSTAGE_WORDS * 4)  // 73,728 B

__device__ __forceinline__ void gemm_load_stage(
    unsigned* sA, unsigned* sB, const unsigned* __restrict__ X,
    const unsigned* __restrict__ W, int bm, int bn, int k0, int lrow, int lcol4)
{
#pragma unroll
    for (int p = 0; p < 2; p++) {
        int row = lrow + p * 64;
        cp_async16(&sA[row * KSTR + lcol4], &X[(size_t)(bm + row) * C_DIM + k0 + lcol4]);
        cp_async16(&sB[row * KSTR + lcol4], &W[(size_t)(bn + row) * C_DIM + k0 + lcol4]);
    }
    cp_commit();
}

template <int HS>
__device__ __forceinline__ void gemm_body(
    const unsigned* __restrict__ X, const unsigned* __restrict__ W,
    const float* __restrict__ bias, void* __restrict__ out,
    int Lrows, int bm, int bn, bool permd, unsigned* gsm)
{
    unsigned* sAr = gsm;
    unsigned* sBr = gsm + 3 * GSTAGE_WORDS;

    const int tid  = threadIdx.x;
    const int wid  = tid >> 5;
    const int lane = tid & 31;
    const int wm   = (wid & 1) * 64;
    const int wn   = (wid >> 1) * 32;
    const int qr   = lane >> 2;
    const int ql   = lane & 3;

    const int lrow  = tid >> 2;
    const int lcol4 = (tid & 3) * 4;

    float acc[4][4][4];
#pragma unroll
    for (int i = 0; i < 4; i++)
#pragma unroll
        for (int j = 0; j < 4; j++)
#pragma unroll
            for (int r = 0; r < 4; r++) acc[i][j][r] = 0.f;

    const int NK = C_DIM / GBK;  // 64

    gemm_load_stage(sAr, sBr, X, W, bm, bn, 0, lrow, lcol4);
    gemm_load_stage(sAr + GSTAGE_WORDS, sBr + GSTAGE_WORDS, X, W, bm, bn, GBK, lrow, lcol4);

    for (int kt = 0; kt < NK; kt++) {
        // Two groups (tiles kt, kt+1) are in flight here. Wait until at most
        // one remains -> tile kt's data has definitely landed. (R8 bug was
        // cp_wait<2> here, which is a no-op with only 2 groups pending.)
        if (kt + 1 < NK) cp_wait<1>(); else cp_wait<0>();
        __syncthreads();

        const int buf = kt % 3;
        if (kt + 2 < NK) {
            const int nb = (kt + 2) % 3;
            gemm_load_stage(sAr + nb * GSTAGE_WORDS, sBr + nb * GSTAGE_WORDS,
                            X, W, bm, bn, (kt + 2) * GBK, lrow, lcol4);
        }

        const unsigned* sA = sAr + buf * GSTAGE_WORDS;
        const unsigned* sB = sBr + buf * GSTAGE_WORDS;

#pragma unroll
        for (int ks = 0; ks < 2; ks++) {
            const int kb = ks * 8;
            unsigned af[4][4], bf[4][2];
#pragma unroll
            for (int mi = 0; mi < 4; mi++) {
                int r0 = wm + mi * 16 + qr;
                uint2 lo = *(const uint2*)&sA[(r0)     * KSTR + kb + 2 * ql];
                uint2 hi = *(const uint2*)&sA[(r0 + 8) * KSTR + kb + 2 * ql];
                af[mi][0] = lo.x;
                af[mi][1] = hi.x;
                af[mi][2] = lo.y;
                af[mi][3] = hi.y;
            }
#pragma unroll
            for (int ni = 0; ni < 4; ni++) {
                int c0 = wn + ni * 8 + qr;
                uint2 bb = *(const uint2*)&sB[c0 * KSTR + kb + 2 * ql];
                bf[ni][0] = bb.x;
                bf[ni][1] = bb.y;
            }
#pragma unroll
            for (int mi = 0; mi < 4; mi++)
#pragma unroll
                for (int ni = 0; ni < 4; ni++)
                    mma_tf32(acc[mi][ni], af[mi], bf[ni]);
        }
    }

    // Epilogue
#pragma unroll
    for (int mi = 0; mi < 4; mi++) {
#pragma unroll
        for (int ni = 0; ni < 4; ni++) {
            const int m0 = bm + wm + mi * 16 + qr;
            const int n0 = bn + wn + ni * 8 + 2 * ql;
            const float b0 = bias[n0], b1 = bias[n0 + 1];
            const float v00 = acc[mi][ni][0] + b0;
            const float v01 = acc[mi][ni][1] + b1;
            const float v10 = acc[mi][ni][2] + b0;
            const float v11 = acc[mi][ni][3] + b1;
            if (HS) {
                unsigned* op = (unsigned*)out;
                const int h  = n0 >> 6;
                const int d  = n0 & 63;
                const int d0 = permd ? kperm8(d)     : d;
                const int d1 = permd ? kperm8(d + 1) : d + 1;
                const int bz = m0 / Lrows;
                const int l  = m0 - bz * Lrows;
                size_t base = (((size_t)(bz * H_HEADS + h) * Lrows) + l) * D_HEAD;
                op[base + d0] = f2tf(v00);
                op[base + d1] = f2tf(v01);
                const int bz2 = (m0 + 8) / Lrows;
                const int l2  = (m0 + 8) - bz2 * Lrows;
                size_t base2 = (((size_t)(bz2 * H_HEADS + h) * Lrows) + l2) * D_HEAD;
                op[base2 + d0] = f2tf(v10);
                op[base2 + d1] = f2tf(v11);
            } else {
                float* op = (float*)out;
                op[(size_t)m0 * C_DIM + n0]           = v00;
                op[(size_t)m0 * C_DIM + n0 + 1]       = v01;
                op[(size_t)(m0 + 8) * C_DIM + n0]     = v10;
                op[(size_t)(m0 + 8) * C_DIM + n0 + 1] = v11;
            }
        }
    }
}

// Fused Q/K/V projections: 1152 CTA-tiles in one launch (kills wave tails).
// Tiles 0..511 = K proj, 512..1023 = V proj, 1024..1151 = Q proj.
__global__ __launch_bounds__(256, 2)
void qkv_proj_kernel(const float* __restrict__ Wq_b, const float* __restrict__ Wk_b,
                     const float* __restrict__ Wv_b)
{
    extern __shared__ unsigned gsm[];
    int t = blockIdx.x;
    const unsigned *X, *W;
    const float* bias;
    unsigned* out;
    int Lrows;
    bool permd;
    if (t < 512) {
        X = g_xk; W = g_wt + 1 * C_DIM * C_DIM; bias = Wk_b;
        out = g_k; Lrows = LK; permd = true;
    } else if (t < 1024) {
        t -= 512;
        X = g_xv; W = g_wt + 2 * C_DIM * C_DIM; bias = Wv_b;
        out = g_v; Lrows = LK; permd = false;
    } else {
        t -= 1024;
        X = g_xq; W = g_wt; bias = Wq_b;
        out = g_q; Lrows = LQ; permd = true;
    }
    const int bm = (t >> 3) * GBM;
    const int bn = (t & 7) * GBN;
    gemm_body<1>(X, W, bias, out, Lrows, bm, bn, permd, gsm);
}

// O projection (separate: depends on flash output)
__global__ __launch_bounds__(256, 2)
void oproj_kernel(const float* __restrict__ Wo_b, float* __restrict__ out)
{
    extern __shared__ unsigned gsm[];
    const int bm = blockIdx.y * GBM;
    const int bn = blockIdx.x * GBN;
    gemm_body<0>(g_ctx, g_wt + 3 * C_DIM * C_DIM, Wo_b, out, 1, bm, bn, false, gsm);
}

// ---------------------------------------------------------------------------
// Flash attention. g_q/g_k are d-permuted -> S-loop fragments via LDS.64.
// S C-fragments feed PV directly (row-permuted V). 2 CTAs/SM, split K/V
// cp.async pipeline, log2-domain softmax.
// ---------------------------------------------------------------------------
#define QT 128
#define KCH 64
#define SQ_STR 72   // stride ≡ 8 (mod 32): conflict-free uint2 fragment loads
#define SV_STR 72
#define FLASH_SMEM_WORDS (QT * SQ_STR + KCH * SQ_STR + KCH * SV_STR + KCH)
#define FLASH_SMEM_BYTES (FLASH_SMEM_WORDS * 4)   // 73,984 B
#define LOG2E 1.4426950408889634f

__device__ __forceinline__ int v_perm_row(int row) {
    int j = row & 7;
    return (row & ~7) + ((j & 1) ? (j >> 1) + 4 : (j >> 1));
}

__global__ __launch_bounds__(256, 2)
void flash_kernel(const float* __restrict__ biasAll)
{
    extern __shared__ unsigned smu[];
    unsigned* uQ    = smu;
    unsigned* uK    = uQ + QT * SQ_STR;
    unsigned* uV    = uK + KCH * SQ_STR;
    float*    fBias = (float*)(uV + KCH * SV_STR);

    const int tid  = threadIdx.x;
    const int w    = tid >> 5;
    const int lane = tid & 31;
    const int qr   = lane >> 2;
    const int ql   = lane & 3;
    const int q0   = blockIdx.x * QT;
    const int h    = blockIdx.y;
    const int b    = blockIdx.z;

    const unsigned* qp = g_q + (size_t)(b * H_HEADS + h) * LQ * D_HEAD;
    const unsigned* kp = g_k + (size_t)(b * H_HEADS + h) * LK * D_HEAD;
    const unsigned* vp = g_v + (size_t)(b * H_HEADS + h) * LK * D_HEAD;
    const float*    bp = biasAll + (size_t)b * LK;

#pragma unroll
    for (int it = 0; it < 8; it++) {
        int f = tid + it * 256;
        int row = f >> 4;
        int c4  = (f & 15) * 4;
        cp_async16(&uQ[row * SQ_STR + c4], &qp[(size_t)(q0 + row) * D_HEAD + c4]);
    }
#pragma unroll
    for (int it = 0; it < 4; it++) {
        int f = tid + it * 256;
        int row = f >> 4;
        int c4  = (f & 15) * 4;
        cp_async16(&uK[row * SQ_STR + c4], &kp[(size_t)row * D_HEAD + c4]);
    }
    if (tid < 16) cp_async16(&fBias[tid * 4], &bp[tid * 4]);
    cp_commit();
#pragma unroll
    for (int it = 0; it < 4; it++) {
        int f = tid + it * 256;
        int row = f >> 4;
        int c4  = (f & 15) * 4;
        cp_async16(&uV[v_perm_row(row) * SV_STR + c4], &vp[(size_t)row * D_HEAD + c4]);
    }
    cp_commit();

    float o[8][4];
#pragma unroll
    for (int ni = 0; ni < 8; ni++)
#pragma unroll
        for (int r = 0; r < 4; r++) o[ni][r] = 0.f;

    float row_m[2] = {-1e30f, -1e30f};
    float row_l[2] = {0.f, 0.f};
    const float scl = 0.125f * LOG2E;
    const int r0 = w * 16 + qr;

    const int NCH = LK / KCH;
    for (int i = 0; i < NCH; i++) {
        const int kc0 = i * KCH;

        cp_wait<1>();
        if (tid < 16) {
            float4 bv = *(float4*)&fBias[tid * 4];
            bv.x *= LOG2E; bv.y *= LOG2E; bv.z *= LOG2E; bv.w *= LOG2E;
            *(float4*)&fBias[tid * 4] = bv;
        }
        __syncthreads();   // #1: K + bias visible

        // ---- S = Q @ K^T (d-permuted operands -> LDS.64 fragments) ----
        float s[8][4];
#pragma unroll
        for (int ni = 0; ni < 8; ni++)
#pragma unroll
            for (int r = 0; r < 4; r++) s[ni][r] = 0.f;

#pragma unroll
        for (int kk = 0; kk < 8; kk++) {
            const int kb = kk * 8;
            uint2 a0 = *(const uint2*)&uQ[(r0)     * SQ_STR + kb + 2 * ql];
            uint2 a1 = *(const uint2*)&uQ[(r0 + 8) * SQ_STR + kb + 2 * ql];
            unsigned af[4];
            af[0] = a0.x;
            af[1] = a1.x;
            af[2] = a0.y;
            af[3] = a1.y;
#pragma unroll
            for (int ni = 0; ni < 8; ni++) {
                const int nc = ni * 8 + qr;
                uint2 bb = *(const uint2*)&uK[nc * SQ_STR + kb + 2 * ql];
                unsigned bf[2];
                bf[0] = bb.x;
                bf[1] = bb.y;
                mma_tf32(s[ni], af, bf);
            }
        }

#pragma unroll
        for (int ni = 0; ni < 8; ni++) {
            const int c0 = ni * 8 + 2 * ql;
            const float b0 = fBias[c0], b1 = fBias[c0 + 1];
            s[ni][0] = fmaf(s[ni][0], scl, b0);
            s[ni][1] = fmaf(s[ni][1], scl, b1);
            s[ni][2] = fmaf(s[ni][2], scl, b0);
            s[ni][3] = fmaf(s[ni][3], scl, b1);
        }
        __syncthreads();   // #2: done with K + bias

        if (i + 1 < NCH) {
#pragma unroll
            for (int it = 0; it < 4; it++) {
                int f = tid + it * 256;
                int row = f >> 4;
                int c4  = (f & 15) * 4;
                cp_async16(&uK[row * SQ_STR + c4],
                           &kp[(size_t)(kc0 + KCH + row) * D_HEAD + c4]);
            }
            if (tid < 16) cp_async16(&fBias[tid * 4], &bp[kc0 + KCH + tid * 4]);
            cp_commit();
        }

        // ---- online softmax ----
#pragma unroll
        for (int half = 0; half < 2; half++) {
            float mx = -1e30f;
#pragma unroll
            for (int ni = 0; ni < 8; ni++)
                mx = fmaxf(mx, fmaxf(s[ni][2 * half], s[ni][2 * half + 1]));
            mx = fmaxf(mx, __shfl_xor_sync(0xffffffffu, mx, 1));
            mx = fmaxf(mx, __shfl_xor_sync(0xffffffffu, mx, 2));
            const float mnew  = fmaxf(row_m[half], mx);
            const float alpha = ex2f(row_m[half] - mnew);
            row_m[half] = mnew;
            float ls = 0.f;
#pragma unroll
            for (int ni = 0; ni < 8; ni++) {
                float e0 = ex2f(s[ni][2 * half]     - mnew);
                float e1 = ex2f(s[ni][2 * half + 1] - mnew);
                s[ni][2 * half]     = e0;
                s[ni][2 * half + 1] = e1;
                ls += e0 + e1;
            }
            ls += __shfl_xor_sync(0xffffffffu, ls, 1);
            ls += __shfl_xor_sync(0xffffffffu, ls, 2);
            row_l[half] = row_l[half] * alpha + ls;
#pragma unroll
            for (int ni = 0; ni < 8; ni++) {
                o[ni][2 * half]     *= alpha;
                o[ni][2 * half + 1] *= alpha;
            }
        }

        if (i + 1 < NCH) cp_wait<1>(); else cp_wait<0>();
        __syncthreads();   // #3: V visible

        // ---- O += P @ V (C-frag -> A-frag direct reuse) ----
#pragma unroll
        for (int kk = 0; kk < 8; kk++) {
            const int kb = kk * 8;
            unsigned af[4];
            af[0] = f2tf(s[kk][0]);
            af[1] = f2tf(s[kk][2]);
            af[2] = f2tf(s[kk][1]);
            af[3] = f2tf(s[kk][3]);
#pragma unroll
            for (int ni = 0; ni < 8; ni++) {
                unsigned bf[2];
                const int nc = ni * 8 + qr;
                bf[0] = uV[(kb + ql)     * SV_STR + nc];
                bf[1] = uV[(kb + ql + 4) * SV_STR + nc];
                mma_tf32(o[ni], af, bf);
            }
        }
        __syncthreads();   // #4: done with V

        if (i + 1 < NCH) {
#pragma unroll
            for (int it = 0; it < 4; it++) {
                int f = tid + it * 256;
                int row = f >> 4;
                int c4  = (f & 15) * 4;
                cp_async16(&uV[v_perm_row(row) * SV_STR + c4],
                           &vp[(size_t)(kc0 + KCH + row) * D_HEAD + c4]);
            }
            cp_commit();
        }
    }

    // ---- normalize; write ctx as tf32 bits in k-PERMUTED layout ----
    const float inv0 = __fdividef(1.f, row_l[0]);
    const float inv1 = __fdividef(1.f, row_l[1]);
    unsigned* ctx = g_ctx + (size_t)b * LQ * C_DIM;
    const int rA = q0 + r0;
#pragma unroll
    for (int ni = 0; ni < 8; ni++) {
        const int col = h * 64 + ni * 8 + 2 * ql;
        const int p0 = kperm8(col);
        const int p1 = kperm8(col + 1);
        ctx[(size_t)rA * C_DIM + p0]       = f2tf(o[ni][0] * inv0);
        ctx[(size_t)rA * C_DIM + p1]       = f2tf(o[ni][1] * inv0);
        ctx[(size_t)(rA + 8) * C_DIM + p0] = f2tf(o[ni][2] * inv1);
        ctx[(size_t)(rA + 8) * C_DIM + p1] = f2tf(o[ni][3] * inv1);
    }
}

// ---------------------------------------------------------------------------
// kernel_launch: 4 stream-ordered launches (graph-capturable, alloc-free)
// ---------------------------------------------------------------------------
extern "C" void kernel_launch(void* const* d_in, const int* in_sizes, int n_in,
                              void* d_out, int out_size)
{
    const float* Q      = (const float*)d_in[0];
    const float* K_in   = (const float*)d_in[1];
    const float* V_in   = (const float*)d_in[2];
    const float* V_bias = (const float*)d_in[3];
    const float* Wq_b   = (const float*)d_in[5];
    const float* Wk_b   = (const float*)d_in[7];
    const float* Wv_b   = (const float*)d_in[9];
    const float* Wo_b   = (const float*)d_in[11];

    cudaFuncSetAttribute(flash_kernel,
                         cudaFuncAttributeMaxDynamicSharedMemorySize, FLASH_SMEM_BYTES);
    cudaFuncSetAttribute(qkv_proj_kernel,
                         cudaFuncAttributeMaxDynamicSharedMemorySize, GEMM_SMEM_BYTES);
    cudaFuncSetAttribute(oproj_kernel,
                         cudaFuncAttributeMaxDynamicSharedMemorySize, GEMM_SMEM_BYTES);

    // Pre-convert X inputs and weights to tf32 bits, k-permuted.
    precvt_kernel<<<1184, 512>>>((const float4*)Q, (const float4*)K_in,
                                 (const float4*)V_in, (const float4*)d_in[4],
                                 (const float4*)d_in[6], (const float4*)d_in[8],
                                 (const float4*)d_in[10]);

    // Fused Q/K/V projections (one launch, 1152 tiles)
    qkv_proj_kernel<<<1152, 256, GEMM_SMEM_BYTES>>>(Wq_b, Wk_b, Wv_b);

    // Attention
    flash_kernel<<<dim3(LQ / QT, H_HEADS, B_BATCH), 256, FLASH_SMEM_BYTES>>>(V_bias);

    // Output projection
    oproj_kernel<<<dim3(C_DIM / GBN, (B_BATCH * LQ) / GBM), 256, GEMM_SMEM_BYTES>>>(
        Wo_b, (float*)d_out);
}